// round 1
// baseline (speedup 1.0000x reference)
#include <cuda_runtime.h>
#include <cstdint>

#define N_NODES 131072
#define N_EDGES 2097152
#define N_GRAPHS 64
#define DIN 64
#define HDIM 128
#define EPSV 1e-5f

// ---------------- scratch (device globals: allocation-free) ----------------
__device__ __align__(128) float d_h[(size_t)N_NODES * HDIM];    // 64 MB
__device__ __align__(128) float d_agg[(size_t)N_NODES * HDIM];  // 64 MB
__device__ __align__(128) float d_deg[N_NODES];                 // holds 1/max(deg,1) after input kernel
__device__ __align__(128) float d_gsum[N_GRAPHS * HDIM];
__device__ __align__(128) float d_gcnt[N_GRAPHS];

// ---------------- helpers ----------------
__device__ __forceinline__ void fma2(unsigned long long& d, unsigned long long a, unsigned long long b) {
    asm("fma.rn.f32x2 %0, %1, %2, %0;" : "+l"(d) : "l"(a), "l"(b));
}
__device__ __forceinline__ unsigned long long pack2(float a) {
    unsigned long long r;
    asm("mov.b64 %0, {%1, %1};" : "=l"(r) : "f"(a));
    return r;
}
__device__ __forceinline__ void unpack2(unsigned long long v, float& lo, float& hi) {
    asm("mov.b64 {%0, %1}, %2;" : "=f"(lo), "=f"(hi) : "l"(v));
}
__device__ __forceinline__ void red4(float* p, float4 v) {
    asm volatile("red.global.add.v4.f32 [%0], {%1,%2,%3,%4};"
                 :: "l"(p), "f"(v.x), "f"(v.y), "f"(v.z), "f"(v.w) : "memory");
}

// ---------------- K0: zero deg / gsum / gcnt ----------------
__global__ void zero_kernel() {
    int i = blockIdx.x * blockDim.x + threadIdx.x;
    if (i < N_NODES) d_deg[i] = 0.0f;
    if (i < N_GRAPHS * HDIM) d_gsum[i] = 0.0f;
    if (i < N_GRAPHS) d_gcnt[i] = 0.0f;
}

// ---------------- K1: degree (segment count on row) ----------------
__global__ void deg_kernel(const int* __restrict__ row) {
    int e = blockIdx.x * blockDim.x + threadIdx.x;
    if (e < N_EDGES) atomicAdd(&d_deg[row[e]], 1.0f);
}

// ---------------- K2: h = x @ W_in + b_in ; zero agg ; deg -> invdeg ----------------
// block = 256 threads, 64 nodes/block. tx = col-quad (0..31), ty = 8-row group (0..7)
__global__ __launch_bounds__(256) void input_kernel(const float* __restrict__ x,
                                                    const float* __restrict__ W,
                                                    const float* __restrict__ b) {
    __shared__ __align__(16) float sX[64 * DIN];
    int tid = threadIdx.x;
    int tx = tid & 31, ty = tid >> 5;
    int nb = blockIdx.x * 64;

    // stage x tile [64 x 64]
#pragma unroll
    for (int j = 0; j < 4; j++) {
        int q = tid + 256 * j;          // float4 quad index 0..1023
        int n = q >> 4, cq = q & 15;
        *(float4*)&sX[n * DIN + 4 * cq] =
            *(const float4*)&x[(size_t)(nb + n) * DIN + 4 * cq];
    }
    __syncthreads();

    unsigned long long acc[8][2];
#pragma unroll
    for (int i = 0; i < 8; i++) { acc[i][0] = 0ull; acc[i][1] = 0ull; }

#pragma unroll 4
    for (int k = 0; k < DIN; k++) {
        ulonglong2 wv = __ldg((const ulonglong2*)(W + (size_t)k * HDIM + 4 * tx));
#pragma unroll
        for (int i = 0; i < 8; i++) {
            unsigned long long a2 = pack2(sX[(ty * 8 + i) * DIN + k]);
            fma2(acc[i][0], a2, wv.x);
            fma2(acc[i][1], a2, wv.y);
        }
    }

    float4 bb = __ldg((const float4*)(b + 4 * tx));
    float4 z4 = make_float4(0.f, 0.f, 0.f, 0.f);
#pragma unroll
    for (int i = 0; i < 8; i++) {
        float4 o;
        unpack2(acc[i][0], o.x, o.y);
        unpack2(acc[i][1], o.z, o.w);
        o.x += bb.x; o.y += bb.y; o.z += bb.z; o.w += bb.w;
        size_t off = (size_t)(nb + ty * 8 + i) * HDIM + 4 * tx;
        *(float4*)&d_h[off] = o;
        *(float4*)&d_agg[off] = z4;   // pre-zero agg for first scatter
    }
    if (tid < 64) {
        int n = nb + tid;
        d_deg[n] = 1.0f / fmaxf(d_deg[n], 1.0f);
    }
}

// ---------------- K3: edge scatter: agg[row] += h[col] * (attr @ W_edge + b_edge) ----------------
// warp per edge; lane handles 4 consecutive channels (float4). E % 8 == 0.
__global__ __launch_bounds__(256) void scatter_kernel(const int* __restrict__ row,
                                                      const int* __restrict__ col,
                                                      const float* __restrict__ eattr,
                                                      const float* __restrict__ We,
                                                      const float* __restrict__ be) {
    int lane = threadIdx.x & 31;
    int e = blockIdx.x * 8 + (threadIdx.x >> 5);

    float4 w0 = __ldg((const float4*)(We + 4 * lane));         // W_edge[0][4l..]
    float4 w1 = __ldg((const float4*)(We + HDIM + 4 * lane));  // W_edge[1][4l..]
    float4 bb = __ldg((const float4*)(be + 4 * lane));

    int r = __ldg(row + e);
    int c = __ldg(col + e);
    float2 a = __ldg(((const float2*)eattr) + e);

    float4 h4 = __ldg(((const float4*)(d_h + (size_t)c * HDIM)) + lane);

    float4 m;
    m.x = h4.x * fmaf(a.x, w0.x, fmaf(a.y, w1.x, bb.x));
    m.y = h4.y * fmaf(a.x, w0.y, fmaf(a.y, w1.y, bb.y));
    m.z = h4.z * fmaf(a.x, w0.z, fmaf(a.y, w1.z, bb.z));
    m.w = h4.w * fmaf(a.x, w0.w, fmaf(a.y, w1.w, bb.w));

    red4(d_agg + (size_t)r * HDIM + 4 * lane, m);
}

// ---------------- K4: fused  t = h + agg*invdeg ;  h = relu(BN(t @ W + b)) ; agg = 0 ----------------
__global__ __launch_bounds__(256) void layer_kernel(const float* __restrict__ W,
                                                    const float* __restrict__ b,
                                                    const float* __restrict__ gamma,
                                                    const float* __restrict__ beta,
                                                    const float* __restrict__ mean,
                                                    const float* __restrict__ var) {
    __shared__ __align__(16) float sA[64 * HDIM];
    int tid = threadIdx.x;
    int tx = tid & 31, ty = tid >> 5;
    int nb = blockIdx.x * 64;
    float4 z4 = make_float4(0.f, 0.f, 0.f, 0.f);

    // build A tile: t = h + agg * invdeg, and re-zero agg for next layer's scatter
#pragma unroll
    for (int j = 0; j < 8; j++) {
        int q = tid + 256 * j;       // quad index 0..2047
        int n = q >> 5, cq = q & 31; // n constant across warp, cq = lane
        size_t off = (size_t)(nb + n) * HDIM + 4 * cq;
        float inv = __ldg(&d_deg[nb + n]);
        float4 h4 = *(const float4*)&d_h[off];
        float4 a4 = *(const float4*)&d_agg[off];
        float4 t;
        t.x = fmaf(a4.x, inv, h4.x);
        t.y = fmaf(a4.y, inv, h4.y);
        t.z = fmaf(a4.z, inv, h4.z);
        t.w = fmaf(a4.w, inv, h4.w);
        *(float4*)&sA[n * HDIM + 4 * cq] = t;
        *(float4*)&d_agg[off] = z4;
    }
    __syncthreads();

    unsigned long long acc[8][2];
#pragma unroll
    for (int i = 0; i < 8; i++) { acc[i][0] = 0ull; acc[i][1] = 0ull; }

#pragma unroll 4
    for (int k = 0; k < HDIM; k++) {
        ulonglong2 wv = __ldg((const ulonglong2*)(W + (size_t)k * HDIM + 4 * tx));
#pragma unroll
        for (int i = 0; i < 8; i++) {
            unsigned long long a2 = pack2(sA[(ty * 8 + i) * HDIM + k]);
            fma2(acc[i][0], a2, wv.x);
            fma2(acc[i][1], a2, wv.y);
        }
    }

    // folded BN:  out = y*sc + sh ; sc = gamma*rsqrt(var+eps) ; sh = (b - mean)*sc + beta
    float4 g4 = __ldg((const float4*)(gamma + 4 * tx));
    float4 e4 = __ldg((const float4*)(beta + 4 * tx));
    float4 m4 = __ldg((const float4*)(mean + 4 * tx));
    float4 v4 = __ldg((const float4*)(var + 4 * tx));
    float4 b4 = __ldg((const float4*)(b + 4 * tx));
    float4 sc, sh;
    sc.x = g4.x * rsqrtf(v4.x + EPSV);
    sc.y = g4.y * rsqrtf(v4.y + EPSV);
    sc.z = g4.z * rsqrtf(v4.z + EPSV);
    sc.w = g4.w * rsqrtf(v4.w + EPSV);
    sh.x = fmaf(b4.x - m4.x, sc.x, e4.x);
    sh.y = fmaf(b4.y - m4.y, sc.y, e4.y);
    sh.z = fmaf(b4.z - m4.z, sc.z, e4.z);
    sh.w = fmaf(b4.w - m4.w, sc.w, e4.w);

#pragma unroll
    for (int i = 0; i < 8; i++) {
        float4 o;
        unpack2(acc[i][0], o.x, o.y);
        unpack2(acc[i][1], o.z, o.w);
        o.x = fmaxf(fmaf(o.x, sc.x, sh.x), 0.f);
        o.y = fmaxf(fmaf(o.y, sc.y, sh.y), 0.f);
        o.z = fmaxf(fmaf(o.z, sc.z, sh.z), 0.f);
        o.w = fmaxf(fmaf(o.w, sc.w, sh.w), 0.f);
        size_t off = (size_t)(nb + ty * 8 + i) * HDIM + 4 * tx;
        *(float4*)&d_h[off] = o;
    }
}

// ---------------- K5: global mean-pool accumulation (batch is sorted) ----------------
// block = 256 threads handles 512 consecutive nodes. tx = col-quad, ty = node lane.
__global__ __launch_bounds__(256) void pool_kernel(const int* __restrict__ batch) {
    int tx = threadIdx.x & 31;
    int ty = threadIdx.x >> 5;
    int base = blockIdx.x * 512;

    float4 acc = make_float4(0.f, 0.f, 0.f, 0.f);
    float cnt = 0.f;
    int curg = -1;

    for (int j = 0; j < 64; j++) {
        int n = base + ty + j * 8;           // nondecreasing walk -> batch nondecreasing
        int g = __ldg(batch + n);
        if (g != curg) {
            if (curg >= 0) {
                red4(d_gsum + curg * HDIM + 4 * tx, acc);
                if (tx == 0) atomicAdd(&d_gcnt[curg], cnt);
            }
            curg = g;
            acc = make_float4(0.f, 0.f, 0.f, 0.f);
            cnt = 0.f;
        }
        float4 h4 = *(const float4*)&d_h[(size_t)n * HDIM + 4 * tx];
        acc.x += h4.x; acc.y += h4.y; acc.z += h4.z; acc.w += h4.w;
        cnt += 1.f;
    }
    if (curg >= 0) {
        red4(d_gsum + curg * HDIM + 4 * tx, acc);
        if (tx == 0) atomicAdd(&d_gcnt[curg], cnt);
    }
}

// ---------------- K6: head: out = [gsum/cnt | relu(gx@Wgp+bgp)] @ Wgc + bgc ----------------
__global__ __launch_bounds__(128) void final_kernel(const float* __restrict__ gx,
                                                    const float* __restrict__ Wgp,
                                                    const float* __restrict__ bgp,
                                                    const float* __restrict__ Wgc,
                                                    const float* __restrict__ bgc,
                                                    float* __restrict__ out) {
    int g = blockIdx.x;
    int t = threadIdx.x;
    __shared__ float sg[HDIM];
    __shared__ float sgp[32];

    float c = fmaxf(__ldg(&d_gcnt[g]), 1.0f);
    sg[t] = d_gsum[g * HDIM + t] / c;
    if (t < 32) {
        float acc = __ldg(bgp + t);
        for (int d = 0; d < 6; d++)
            acc = fmaf(__ldg(gx + g * 6 + d), __ldg(Wgp + d * 32 + t), acc);
        sgp[t] = fmaxf(acc, 0.f);
    }
    __syncthreads();

    float acc = __ldg(bgc + t);
#pragma unroll 4
    for (int k = 0; k < HDIM; k++)
        acc = fmaf(sg[k], __ldg(Wgc + (size_t)k * HDIM + t), acc);
#pragma unroll 4
    for (int k = 0; k < 32; k++)
        acc = fmaf(sgp[k], __ldg(Wgc + (size_t)(HDIM + k) * HDIM + t), acc);
    out[g * HDIM + t] = acc;
}

// ---------------- launch ----------------
extern "C" void kernel_launch(void* const* d_in, const int* in_sizes, int n_in,
                              void* d_out, int out_size) {
    const float* x       = (const float*)d_in[0];
    const float* eattr   = (const float*)d_in[1];
    const float* gx      = (const float*)d_in[2];
    const float* W_in    = (const float*)d_in[3];
    const float* b_in    = (const float*)d_in[4];
    const float* W_edge  = (const float*)d_in[5];
    const float* b_edge  = (const float*)d_in[6];
    const float* W_gcn   = (const float*)d_in[7];
    const float* b_gcn   = (const float*)d_in[8];
    const float* bn_g    = (const float*)d_in[9];
    const float* bn_b    = (const float*)d_in[10];
    const float* bn_m    = (const float*)d_in[11];
    const float* bn_v    = (const float*)d_in[12];
    const float* W_gproj = (const float*)d_in[13];
    const float* b_gproj = (const float*)d_in[14];
    const float* W_gcomb = (const float*)d_in[15];
    const float* b_gcomb = (const float*)d_in[16];
    const int*   row     = (const int*)d_in[17];
    const int*   col     = (const int*)d_in[18];
    const int*   batch   = (const int*)d_in[19];
    float* out = (float*)d_out;

    zero_kernel<<<512, 256>>>();
    deg_kernel<<<N_EDGES / 256, 256>>>(row);
    input_kernel<<<N_NODES / 64, 256>>>(x, W_in, b_in);

    for (int l = 0; l < 3; l++) {
        scatter_kernel<<<N_EDGES / 8, 256>>>(row, col, eattr, W_edge, b_edge);
        layer_kernel<<<N_NODES / 64, 256>>>(W_gcn + (size_t)l * HDIM * HDIM,
                                            b_gcn + l * HDIM,
                                            bn_g + l * HDIM, bn_b + l * HDIM,
                                            bn_m + l * HDIM, bn_v + l * HDIM);
    }

    pool_kernel<<<N_NODES / 512, 256>>>(batch);
    final_kernel<<<N_GRAPHS, HDIM>>>(gx, W_gproj, b_gproj, W_gcomb, b_gcomb, out);
}

// round 2
// speedup vs baseline: 1.1782x; 1.1782x over previous
#include <cuda_runtime.h>
#include <cstdint>

#define N_NODES 131072
#define N_EDGES 2097152
#define N_GRAPHS 64
#define DIN 64
#define HDIM 128
#define EPSV 1e-5f

// ---------------- scratch (device globals: allocation-free) ----------------
__device__ __align__(128) float d_h[(size_t)N_NODES * HDIM];    // 64 MB
__device__ __align__(128) float d_t[(size_t)N_NODES * HDIM];    // 64 MB
__device__ __align__(128) int    d_colp[N_EDGES];               // permuted col
__device__ __align__(128) float2 d_eap[N_EDGES];                // permuted edge attr
__device__ __align__(128) int   d_degi[N_NODES];
__device__ __align__(128) int   d_cnt[N_NODES];
__device__ __align__(128) int   d_start[N_NODES + 1];
__device__ __align__(128) float d_inv[N_NODES];
__device__ __align__(128) int   d_bsum[128];
__device__ __align__(128) int   d_bbase[128];
__device__ __align__(128) unsigned long long d_wdup[(DIN + 3 * HDIM) * HDIM];
__device__ __align__(128) float d_gsum[N_GRAPHS * HDIM];
__device__ __align__(128) float d_gcnt[N_GRAPHS];

// ---------------- helpers ----------------
__device__ __forceinline__ void fma2(unsigned long long& d, unsigned long long a, unsigned long long b) {
    asm("fma.rn.f32x2 %0, %1, %2, %0;" : "+l"(d) : "l"(a), "l"(b));
}
__device__ __forceinline__ unsigned long long pack2(float a) {
    unsigned long long r;
    asm("mov.b64 %0, {%1, %1};" : "=l"(r) : "f"(a));
    return r;
}
__device__ __forceinline__ void unpack2(unsigned long long v, float& lo, float& hi) {
    asm("mov.b64 {%0, %1}, %2;" : "=f"(lo), "=f"(hi) : "l"(v));
}
__device__ __forceinline__ void red4(float* p, float4 v) {
    asm volatile("red.global.add.v4.f32 [%0], {%1,%2,%3,%4};"
                 :: "l"(p), "f"(v.x), "f"(v.y), "f"(v.z), "f"(v.w) : "memory");
}

// ---------------- K0: zero counters ----------------
__global__ void zero_kernel() {
    int i = blockIdx.x * blockDim.x + threadIdx.x;
    if (i < N_NODES) { d_degi[i] = 0; d_cnt[i] = 0; }
    if (i < N_GRAPHS * HDIM) d_gsum[i] = 0.0f;
    if (i < N_GRAPHS) d_gcnt[i] = 0.0f;
}

// ---------------- K1: degree count ----------------
__global__ void deg_kernel(const int* __restrict__ row) {
    int e = blockIdx.x * blockDim.x + threadIdx.x;
    atomicAdd(&d_degi[row[e]], 1);
}

// ---------------- K2a/b/c: exclusive scan of deg -> d_start, plus d_inv ----------------
__global__ __launch_bounds__(256) void scanA_kernel() {
    __shared__ int sp[256];
    int tid = threadIdx.x;
    int4 dv = ((const int4*)d_degi)[blockIdx.x * 256 + tid];
    int s = dv.x + dv.y + dv.z + dv.w;
    sp[tid] = s;
    __syncthreads();
    for (int off = 128; off > 0; off >>= 1) {
        if (tid < off) sp[tid] += sp[tid + off];
        __syncthreads();
    }
    if (tid == 0) d_bsum[blockIdx.x] = sp[0];
}

__global__ __launch_bounds__(128) void scanB_kernel() {
    __shared__ int sp[128];
    int tid = threadIdx.x;
    int s = d_bsum[tid];
    sp[tid] = s;
    __syncthreads();
    for (int off = 1; off < 128; off <<= 1) {
        int v = (tid >= off) ? sp[tid - off] : 0;
        __syncthreads();
        sp[tid] += v;
        __syncthreads();
    }
    d_bbase[tid] = sp[tid] - s;
    if (tid == 127) d_start[N_NODES] = sp[127];
}

__global__ __launch_bounds__(256) void scanC_kernel() {
    __shared__ int sp[256];
    int tid = threadIdx.x;
    int idx = blockIdx.x * 256 + tid;
    int4 dv = ((const int4*)d_degi)[idx];
    int s = dv.x + dv.y + dv.z + dv.w;
    sp[tid] = s;
    __syncthreads();
    for (int off = 1; off < 256; off <<= 1) {
        int v = (tid >= off) ? sp[tid - off] : 0;
        __syncthreads();
        sp[tid] += v;
        __syncthreads();
    }
    int base = d_bbase[blockIdx.x] + sp[tid] - s;
    int4 st;
    st.x = base;
    st.y = base + dv.x;
    st.z = st.y + dv.y;
    st.w = st.z + dv.z;
    ((int4*)d_start)[idx] = st;
    float4 iv;
    iv.x = 1.0f / (float)max(dv.x, 1);
    iv.y = 1.0f / (float)max(dv.y, 1);
    iv.z = 1.0f / (float)max(dv.z, 1);
    iv.w = 1.0f / (float)max(dv.w, 1);
    ((float4*)d_inv)[idx] = iv;
}

// ---------------- K3: counting-sort edges into CSR order ----------------
__global__ __launch_bounds__(256) void build_kernel(const int* __restrict__ row,
                                                    const int* __restrict__ col,
                                                    const float* __restrict__ eattr) {
    int e = blockIdx.x * blockDim.x + threadIdx.x;
    int r = __ldg(row + e);
    int pos = __ldg(d_start + r) + atomicAdd(&d_cnt[r], 1);
    d_colp[pos] = __ldg(col + e);
    d_eap[pos] = __ldg((const float2*)eattr + e);
}

// ---------------- K4: duplicate-pack all GEMM weights ----------------
__global__ __launch_bounds__(256) void wdup_kernel(const float* __restrict__ Win,
                                                   const float* __restrict__ Wg) {
    int i = blockIdx.x * blockDim.x + threadIdx.x;  // < (64 + 384)*128 = 57344
    float v = (i < DIN * HDIM) ? __ldg(Win + i) : __ldg(Wg + i - DIN * HDIM);
    d_wdup[i] = pack2(v);
}

// ---------------- K5: CSR gather: t[n] = h[n] + (sum_e h[colp]*ew) * inv[n] ----------------
// warp per node; lane = 4 channels.
__global__ __launch_bounds__(256) void gather_kernel(const float* __restrict__ We,
                                                     const float* __restrict__ be) {
    int lane = threadIdx.x & 31;
    int n = blockIdx.x * 8 + (threadIdx.x >> 5);

    float4 w0 = __ldg((const float4*)We + lane);
    float4 w1 = __ldg((const float4*)(We + HDIM) + lane);
    float4 bb = __ldg((const float4*)be + lane);

    int js = __ldg(d_start + n);
    int je = __ldg(d_start + n + 1);

    const float4* h4 = (const float4*)d_h;
    float4 acc0 = make_float4(0.f, 0.f, 0.f, 0.f);
    float4 acc1 = make_float4(0.f, 0.f, 0.f, 0.f);

    int j = js;
    while (j + 2 <= je) {
        int c0 = __ldg(d_colp + j);
        int c1 = __ldg(d_colp + j + 1);
        float2 a0 = __ldg(d_eap + j);
        float2 a1 = __ldg(d_eap + j + 1);
        float4 v0 = h4[(size_t)c0 * 32 + lane];
        float4 v1 = h4[(size_t)c1 * 32 + lane];
        float4 e0, e1;
        e0.x = fmaf(a0.x, w0.x, fmaf(a0.y, w1.x, bb.x));
        e0.y = fmaf(a0.x, w0.y, fmaf(a0.y, w1.y, bb.y));
        e0.z = fmaf(a0.x, w0.z, fmaf(a0.y, w1.z, bb.z));
        e0.w = fmaf(a0.x, w0.w, fmaf(a0.y, w1.w, bb.w));
        e1.x = fmaf(a1.x, w0.x, fmaf(a1.y, w1.x, bb.x));
        e1.y = fmaf(a1.x, w0.y, fmaf(a1.y, w1.y, bb.y));
        e1.z = fmaf(a1.x, w0.z, fmaf(a1.y, w1.z, bb.z));
        e1.w = fmaf(a1.x, w0.w, fmaf(a1.y, w1.w, bb.w));
        acc0.x = fmaf(v0.x, e0.x, acc0.x);
        acc0.y = fmaf(v0.y, e0.y, acc0.y);
        acc0.z = fmaf(v0.z, e0.z, acc0.z);
        acc0.w = fmaf(v0.w, e0.w, acc0.w);
        acc1.x = fmaf(v1.x, e1.x, acc1.x);
        acc1.y = fmaf(v1.y, e1.y, acc1.y);
        acc1.z = fmaf(v1.z, e1.z, acc1.z);
        acc1.w = fmaf(v1.w, e1.w, acc1.w);
        j += 2;
    }
    if (j < je) {
        int c0 = __ldg(d_colp + j);
        float2 a0 = __ldg(d_eap + j);
        float4 v0 = h4[(size_t)c0 * 32 + lane];
        float4 e0;
        e0.x = fmaf(a0.x, w0.x, fmaf(a0.y, w1.x, bb.x));
        e0.y = fmaf(a0.x, w0.y, fmaf(a0.y, w1.y, bb.y));
        e0.z = fmaf(a0.x, w0.z, fmaf(a0.y, w1.z, bb.z));
        e0.w = fmaf(a0.x, w0.w, fmaf(a0.y, w1.w, bb.w));
        acc0.x = fmaf(v0.x, e0.x, acc0.x);
        acc0.y = fmaf(v0.y, e0.y, acc0.y);
        acc0.z = fmaf(v0.z, e0.z, acc0.z);
        acc0.w = fmaf(v0.w, e0.w, acc0.w);
    }
    acc0.x += acc1.x; acc0.y += acc1.y; acc0.z += acc1.z; acc0.w += acc1.w;

    float inv = __ldg(d_inv + n);
    float4 hv = h4[(size_t)n * 32 + lane];
    float4 t;
    t.x = fmaf(acc0.x, inv, hv.x);
    t.y = fmaf(acc0.y, inv, hv.y);
    t.z = fmaf(acc0.z, inv, hv.z);
    t.w = fmaf(acc0.w, inv, hv.w);
    ((float4*)d_t)[(size_t)n * 32 + lane] = t;
}

// ---------------- K6: GEMM  h = epi(A @ W + b) ----------------
// block: 256 thr = 16 tx (col-octets) x 16 ty (row-octets); 128 nodes/block.
// A staged transposed + XOR-swizzled; accumulators are f32x2 row-pairs.
template <int K, bool BN>
__global__ __launch_bounds__(256) void gemm_kernel(const float* __restrict__ Ax,
                                                   int woff,
                                                   const float* __restrict__ bias,
                                                   const float* __restrict__ gamma,
                                                   const float* __restrict__ beta,
                                                   const float* __restrict__ mean,
                                                   const float* __restrict__ var) {
    extern __shared__ float sAT[];  // [K][128] swizzled
    const int tid = threadIdx.x;
    const int tx = tid & 15;
    const int ty = tid >> 4;
    const int nb = blockIdx.x * 128;
    constexpr int KQ = K / 4;

    const float* src = Ax ? Ax : (const float*)d_t;

    // stage A tile transposed with swizzle phys_n = n ^ (2*(kq&15))
#pragma unroll
    for (int j = 0; j < K / 8; j++) {
        int q = tid + 256 * j;
        int n = q / KQ;
        int kq = q % KQ;
        float4 v = *(const float4*)&src[(size_t)(nb + n) * K + 4 * kq];
        int pn = n ^ (2 * (kq & 15));
        sAT[(4 * kq + 0) * 128 + pn] = v.x;
        sAT[(4 * kq + 1) * 128 + pn] = v.y;
        sAT[(4 * kq + 2) * 128 + pn] = v.z;
        sAT[(4 * kq + 3) * 128 + pn] = v.w;
    }
    __syncthreads();

    unsigned long long acc[4][8];
#pragma unroll
    for (int p = 0; p < 4; p++)
#pragma unroll
        for (int c = 0; c < 8; c++) acc[p][c] = 0ull;

    const unsigned long long* Wp = d_wdup + woff + tx * 8;

#pragma unroll 2
    for (int k = 0; k < K; k++) {
        const float* ar = sAT + k * 128;
        int sw = 2 * ((k >> 2) & 15);
        unsigned long long a[4];
#pragma unroll
        for (int p = 0; p < 4; p++)
            a[p] = *(const unsigned long long*)(ar + ((ty * 8 + 2 * p) ^ sw));
        ulonglong2 w01 = __ldg((const ulonglong2*)(Wp + (size_t)k * 128));
        ulonglong2 w23 = __ldg((const ulonglong2*)(Wp + (size_t)k * 128 + 2));
        ulonglong2 w45 = __ldg((const ulonglong2*)(Wp + (size_t)k * 128 + 4));
        ulonglong2 w67 = __ldg((const ulonglong2*)(Wp + (size_t)k * 128 + 6));
        unsigned long long w[8] = {w01.x, w01.y, w23.x, w23.y, w45.x, w45.y, w67.x, w67.y};
#pragma unroll
        for (int p = 0; p < 4; p++)
#pragma unroll
            for (int c = 0; c < 8; c++) fma2(acc[p][c], a[p], w[c]);
    }

    // epilogue
    int c0 = tx * 8;
    float sc[8], sh[8];
    if (BN) {
#pragma unroll
        for (int i = 0; i < 8; i++) {
            float g = __ldg(gamma + c0 + i);
            float v = __ldg(var + c0 + i);
            float m = __ldg(mean + c0 + i);
            float bt = __ldg(beta + c0 + i);
            float b = __ldg(bias + c0 + i);
            sc[i] = g * rsqrtf(v + EPSV);
            sh[i] = fmaf(b - m, sc[i], bt);
        }
    } else {
#pragma unroll
        for (int i = 0; i < 8; i++) { sc[i] = 1.0f; sh[i] = __ldg(bias + c0 + i); }
    }

#pragma unroll
    for (int p = 0; p < 4; p++) {
        float lo[8], hi[8];
#pragma unroll
        for (int c = 0; c < 8; c++) {
            unpack2(acc[p][c], lo[c], hi[c]);
            lo[c] = fmaf(lo[c], sc[c], sh[c]);
            hi[c] = fmaf(hi[c], sc[c], sh[c]);
            if (BN) { lo[c] = fmaxf(lo[c], 0.f); hi[c] = fmaxf(hi[c], 0.f); }
        }
        int r0 = nb + ty * 8 + 2 * p;
        float* o0 = d_h + (size_t)r0 * HDIM + c0;
        float* o1 = o0 + HDIM;
        *(float4*)o0 = make_float4(lo[0], lo[1], lo[2], lo[3]);
        *(float4*)(o0 + 4) = make_float4(lo[4], lo[5], lo[6], lo[7]);
        *(float4*)o1 = make_float4(hi[0], hi[1], hi[2], hi[3]);
        *(float4*)(o1 + 4) = make_float4(hi[4], hi[5], hi[6], hi[7]);
    }
}

// ---------------- K7: global mean-pool (batch sorted) ----------------
__global__ __launch_bounds__(256) void pool_kernel(const int* __restrict__ batch) {
    int tx = threadIdx.x & 31;
    int ty = threadIdx.x >> 5;
    int base = blockIdx.x * 512;

    float4 acc = make_float4(0.f, 0.f, 0.f, 0.f);
    float cnt = 0.f;
    int curg = -1;

    for (int j = 0; j < 64; j++) {
        int n = base + ty + j * 8;
        int g = __ldg(batch + n);
        if (g != curg) {
            if (curg >= 0) {
                red4(d_gsum + curg * HDIM + 4 * tx, acc);
                if (tx == 0) atomicAdd(&d_gcnt[curg], cnt);
            }
            curg = g;
            acc = make_float4(0.f, 0.f, 0.f, 0.f);
            cnt = 0.f;
        }
        float4 h4 = *(const float4*)&d_h[(size_t)n * HDIM + 4 * tx];
        acc.x += h4.x; acc.y += h4.y; acc.z += h4.z; acc.w += h4.w;
        cnt += 1.f;
    }
    if (curg >= 0) {
        red4(d_gsum + curg * HDIM + 4 * tx, acc);
        if (tx == 0) atomicAdd(&d_gcnt[curg], cnt);
    }
}

// ---------------- K8: head ----------------
__global__ __launch_bounds__(128) void final_kernel(const float* __restrict__ gx,
                                                    const float* __restrict__ Wgp,
                                                    const float* __restrict__ bgp,
                                                    const float* __restrict__ Wgc,
                                                    const float* __restrict__ bgc,
                                                    float* __restrict__ out) {
    int g = blockIdx.x;
    int t = threadIdx.x;
    __shared__ float sg[HDIM];
    __shared__ float sgp[32];

    float c = fmaxf(__ldg(&d_gcnt[g]), 1.0f);
    sg[t] = d_gsum[g * HDIM + t] / c;
    if (t < 32) {
        float acc = __ldg(bgp + t);
        for (int d = 0; d < 6; d++)
            acc = fmaf(__ldg(gx + g * 6 + d), __ldg(Wgp + d * 32 + t), acc);
        sgp[t] = fmaxf(acc, 0.f);
    }
    __syncthreads();

    float acc = __ldg(bgc + t);
#pragma unroll 4
    for (int k = 0; k < HDIM; k++)
        acc = fmaf(sg[k], __ldg(Wgc + (size_t)k * HDIM + t), acc);
#pragma unroll 4
    for (int k = 0; k < 32; k++)
        acc = fmaf(sgp[k], __ldg(Wgc + (size_t)(HDIM + k) * HDIM + t), acc);
    out[g * HDIM + t] = acc;
}

// ---------------- launch ----------------
extern "C" void kernel_launch(void* const* d_in, const int* in_sizes, int n_in,
                              void* d_out, int out_size) {
    const float* x       = (const float*)d_in[0];
    const float* eattr   = (const float*)d_in[1];
    const float* gx      = (const float*)d_in[2];
    const float* W_in    = (const float*)d_in[3];
    const float* b_in    = (const float*)d_in[4];
    const float* W_edge  = (const float*)d_in[5];
    const float* b_edge  = (const float*)d_in[6];
    const float* W_gcn   = (const float*)d_in[7];
    const float* b_gcn   = (const float*)d_in[8];
    const float* bn_g    = (const float*)d_in[9];
    const float* bn_b    = (const float*)d_in[10];
    const float* bn_m    = (const float*)d_in[11];
    const float* bn_v    = (const float*)d_in[12];
    const float* W_gproj = (const float*)d_in[13];
    const float* b_gproj = (const float*)d_in[14];
    const float* W_gcomb = (const float*)d_in[15];
    const float* b_gcomb = (const float*)d_in[16];
    const int*   row     = (const int*)d_in[17];
    const int*   col     = (const int*)d_in[18];
    const int*   batch   = (const int*)d_in[19];
    float* out = (float*)d_out;

    cudaFuncSetAttribute(gemm_kernel<HDIM, true>,
                         cudaFuncAttributeMaxDynamicSharedMemorySize, HDIM * 128 * 4);
    cudaFuncSetAttribute(gemm_kernel<DIN, false>,
                         cudaFuncAttributeMaxDynamicSharedMemorySize, DIN * 128 * 4);

    zero_kernel<<<512, 256>>>();
    deg_kernel<<<N_EDGES / 256, 256>>>(row);
    scanA_kernel<<<128, 256>>>();
    scanB_kernel<<<1, 128>>>();
    scanC_kernel<<<128, 256>>>();
    build_kernel<<<N_EDGES / 256, 256>>>(row, col, eattr);
    wdup_kernel<<<(DIN + 3 * HDIM) * HDIM / 256, 256>>>(W_in, W_gcn);

    gemm_kernel<DIN, false><<<N_NODES / 128, 256, DIN * 128 * 4>>>(
        x, 0, b_in, nullptr, nullptr, nullptr, nullptr);

    for (int l = 0; l < 3; l++) {
        gather_kernel<<<N_NODES / 8, 256>>>(W_edge, b_edge);
        gemm_kernel<HDIM, true><<<N_NODES / 128, 256, HDIM * 128 * 4>>>(
            nullptr, DIN * HDIM + l * HDIM * HDIM, b_gcn + l * HDIM,
            bn_g + l * HDIM, bn_b + l * HDIM, bn_m + l * HDIM, bn_v + l * HDIM);
    }

    pool_kernel<<<N_NODES / 512, 256>>>(batch);
    final_kernel<<<N_GRAPHS, HDIM>>>(gx, W_gproj, b_gproj, W_gcomb, b_gcomb, out);
}

// round 3
// speedup vs baseline: 1.2249x; 1.0397x over previous
#include <cuda_runtime.h>
#include <cuda_fp16.h>
#include <cstdint>

#define N_NODES 131072
#define N_EDGES 2097152
#define N_GRAPHS 64
#define DIN 64
#define HDIM 128
#define EPSV 1e-5f

// ---------------- scratch (device globals: allocation-free) ----------------
__device__ __align__(128) float  d_h[(size_t)N_NODES * HDIM];    // 64 MB
__device__ __align__(128) __half d_h16[(size_t)N_NODES * HDIM];  // 32 MB (L2-resident gather table)
__device__ __align__(128) float  d_t[(size_t)N_NODES * HDIM];    // 64 MB (streamed)
__device__ __align__(128) int    d_colp[N_EDGES];
__device__ __align__(128) float2 d_eap[N_EDGES];
__device__ __align__(128) int    d_degi[N_NODES];
__device__ __align__(128) int    d_cnt[N_NODES];
__device__ __align__(128) int    d_start[N_NODES + 1];
__device__ __align__(128) float  d_inv[N_NODES];
__device__ __align__(128) int    d_bsum[128];
__device__ __align__(128) int    d_bbase[128];
__device__ __align__(128) unsigned long long d_wdup[(DIN + 3 * HDIM) * HDIM];
__device__ __align__(128) float  d_gsum[N_GRAPHS * HDIM];
__device__ __align__(128) float  d_gcnt[N_GRAPHS];

// ---------------- helpers ----------------
__device__ __forceinline__ void fma2(unsigned long long& d, unsigned long long a, unsigned long long b) {
    asm("fma.rn.f32x2 %0, %1, %2, %0;" : "+l"(d) : "l"(a), "l"(b));
}
__device__ __forceinline__ unsigned long long pack2(float a) {
    unsigned long long r;
    asm("mov.b64 %0, {%1, %1};" : "=l"(r) : "f"(a));
    return r;
}
__device__ __forceinline__ void unpack2(unsigned long long v, float& lo, float& hi) {
    asm("mov.b64 {%0, %1}, %2;" : "=f"(lo), "=f"(hi) : "l"(v));
}
__device__ __forceinline__ void red4(float* p, float4 v) {
    asm volatile("red.global.add.v4.f32 [%0], {%1,%2,%3,%4};"
                 :: "l"(p), "f"(v.x), "f"(v.y), "f"(v.z), "f"(v.w) : "memory");
}
// fp16 gather row read: 8 bytes/lane = 4 channels
__device__ __forceinline__ float4 ld_h16(int c, int lane) {
    uint2 u = __ldg((const uint2*)(d_h16 + (size_t)c * HDIM) + lane);
    __half2* p = (__half2*)&u;
    float2 f0 = __half22float2(p[0]);
    float2 f1 = __half22float2(p[1]);
    return make_float4(f0.x, f0.y, f1.x, f1.y);
}

// ---------------- K0: zero counters ----------------
__global__ void zero_kernel() {
    int i = blockIdx.x * blockDim.x + threadIdx.x;
    if (i < N_NODES) { d_degi[i] = 0; d_cnt[i] = 0; }
    if (i < N_GRAPHS * HDIM) d_gsum[i] = 0.0f;
    if (i < N_GRAPHS) d_gcnt[i] = 0.0f;
}

// ---------------- K1: degree count ----------------
__global__ void deg_kernel(const int* __restrict__ row) {
    int e = blockIdx.x * blockDim.x + threadIdx.x;
    atomicAdd(&d_degi[row[e]], 1);
}

// ---------------- K2a/b/c: exclusive scan of deg -> d_start, plus d_inv ----------------
__global__ __launch_bounds__(256) void scanA_kernel() {
    __shared__ int sp[256];
    int tid = threadIdx.x;
    int4 dv = ((const int4*)d_degi)[blockIdx.x * 256 + tid];
    int s = dv.x + dv.y + dv.z + dv.w;
    sp[tid] = s;
    __syncthreads();
    for (int off = 128; off > 0; off >>= 1) {
        if (tid < off) sp[tid] += sp[tid + off];
        __syncthreads();
    }
    if (tid == 0) d_bsum[blockIdx.x] = sp[0];
}

__global__ __launch_bounds__(128) void scanB_kernel() {
    __shared__ int sp[128];
    int tid = threadIdx.x;
    int s = d_bsum[tid];
    sp[tid] = s;
    __syncthreads();
    for (int off = 1; off < 128; off <<= 1) {
        int v = (tid >= off) ? sp[tid - off] : 0;
        __syncthreads();
        sp[tid] += v;
        __syncthreads();
    }
    d_bbase[tid] = sp[tid] - s;
    if (tid == 127) d_start[N_NODES] = sp[127];
}

__global__ __launch_bounds__(256) void scanC_kernel() {
    __shared__ int sp[256];
    int tid = threadIdx.x;
    int idx = blockIdx.x * 256 + tid;
    int4 dv = ((const int4*)d_degi)[idx];
    int s = dv.x + dv.y + dv.z + dv.w;
    sp[tid] = s;
    __syncthreads();
    for (int off = 1; off < 256; off <<= 1) {
        int v = (tid >= off) ? sp[tid - off] : 0;
        __syncthreads();
        sp[tid] += v;
        __syncthreads();
    }
    int base = d_bbase[blockIdx.x] + sp[tid] - s;
    int4 st;
    st.x = base;
    st.y = base + dv.x;
    st.z = st.y + dv.y;
    st.w = st.z + dv.z;
    ((int4*)d_start)[idx] = st;
    float4 iv;
    iv.x = 1.0f / (float)max(dv.x, 1);
    iv.y = 1.0f / (float)max(dv.y, 1);
    iv.z = 1.0f / (float)max(dv.z, 1);
    iv.w = 1.0f / (float)max(dv.w, 1);
    ((float4*)d_inv)[idx] = iv;
}

// ---------------- K3: counting-sort edges into CSR order ----------------
__global__ __launch_bounds__(256) void build_kernel(const int* __restrict__ row,
                                                    const int* __restrict__ col,
                                                    const float* __restrict__ eattr) {
    int e = blockIdx.x * blockDim.x + threadIdx.x;
    int r = __ldg(row + e);
    int pos = __ldg(d_start + r) + atomicAdd(&d_cnt[r], 1);
    d_colp[pos] = __ldg(col + e);
    d_eap[pos] = __ldg((const float2*)eattr + e);
}

// ---------------- K4: duplicate-pack all GEMM weights ----------------
__global__ __launch_bounds__(256) void wdup_kernel(const float* __restrict__ Win,
                                                   const float* __restrict__ Wg) {
    int i = blockIdx.x * blockDim.x + threadIdx.x;
    float v = (i < DIN * HDIM) ? __ldg(Win + i) : __ldg(Wg + i - DIN * HDIM);
    d_wdup[i] = pack2(v);
}

// ---------------- K5: CSR gather: t[n] = h[n] + (sum_e h16[colp]*ew) * inv[n] ----------------
// warp per node; lane = 4 channels; 4 edges in flight.
__global__ __launch_bounds__(256) void gather_kernel(const float* __restrict__ We,
                                                     const float* __restrict__ be) {
    int lane = threadIdx.x & 31;
    int n = blockIdx.x * 8 + (threadIdx.x >> 5);

    float4 w0 = __ldg((const float4*)We + lane);
    float4 w1 = __ldg((const float4*)(We + HDIM) + lane);
    float4 bb = __ldg((const float4*)be + lane);

    int js = __ldg(d_start + n);
    int je = __ldg(d_start + n + 1);

    float4 acc = make_float4(0.f, 0.f, 0.f, 0.f);

    int j = js;
    for (; j + 4 <= je; j += 4) {
        int c0 = __ldg(d_colp + j);
        int c1 = __ldg(d_colp + j + 1);
        int c2 = __ldg(d_colp + j + 2);
        int c3 = __ldg(d_colp + j + 3);
        float2 a0 = __ldg(d_eap + j);
        float2 a1 = __ldg(d_eap + j + 1);
        float2 a2 = __ldg(d_eap + j + 2);
        float2 a3 = __ldg(d_eap + j + 3);
        float4 v0 = ld_h16(c0, lane);
        float4 v1 = ld_h16(c1, lane);
        float4 v2 = ld_h16(c2, lane);
        float4 v3 = ld_h16(c3, lane);
#define EDGE(v, a)                                                    \
        {                                                             \
            float4 e;                                                 \
            e.x = fmaf(a.x, w0.x, fmaf(a.y, w1.x, bb.x));             \
            e.y = fmaf(a.x, w0.y, fmaf(a.y, w1.y, bb.y));             \
            e.z = fmaf(a.x, w0.z, fmaf(a.y, w1.z, bb.z));             \
            e.w = fmaf(a.x, w0.w, fmaf(a.y, w1.w, bb.w));             \
            acc.x = fmaf(v.x, e.x, acc.x);                            \
            acc.y = fmaf(v.y, e.y, acc.y);                            \
            acc.z = fmaf(v.z, e.z, acc.z);                            \
            acc.w = fmaf(v.w, e.w, acc.w);                            \
        }
        EDGE(v0, a0) EDGE(v1, a1) EDGE(v2, a2) EDGE(v3, a3)
    }
    for (; j < je; j++) {
        int c0 = __ldg(d_colp + j);
        float2 a0 = __ldg(d_eap + j);
        float4 v0 = ld_h16(c0, lane);
        EDGE(v0, a0)
    }
#undef EDGE

    float inv = __ldg(d_inv + n);
    float4 hv = __ldg((const float4*)(d_h + (size_t)n * HDIM) + lane);
    float4 t;
    t.x = fmaf(acc.x, inv, hv.x);
    t.y = fmaf(acc.y, inv, hv.y);
    t.z = fmaf(acc.z, inv, hv.z);
    t.w = fmaf(acc.w, inv, hv.w);
    __stcs((float4*)(d_t + (size_t)n * HDIM) + lane, t);   // evict-first
}

// ---------------- K6: GEMM  h = epi(A @ W + b) ; also writes fp16 mirror ----------------
template <int K, bool BN>
__global__ __launch_bounds__(256) void gemm_kernel(const float* __restrict__ Ax,
                                                   int woff,
                                                   const float* __restrict__ bias,
                                                   const float* __restrict__ gamma,
                                                   const float* __restrict__ beta,
                                                   const float* __restrict__ mean,
                                                   const float* __restrict__ var) {
    extern __shared__ float sAT[];  // [K][128] swizzled
    const int tid = threadIdx.x;
    const int tx = tid & 15;
    const int ty = tid >> 4;
    const int nb = blockIdx.x * 128;
    constexpr int KQ = K / 4;

    const float* src = Ax ? Ax : (const float*)d_t;

    // stage A tile transposed with swizzle phys_n = n ^ (2*(kq&15)); streaming read
#pragma unroll
    for (int j = 0; j < K / 8; j++) {
        int q = tid + 256 * j;
        int n = q / KQ;
        int kq = q % KQ;
        float4 v = __ldcs((const float4*)&src[(size_t)(nb + n) * K + 4 * kq]);
        int pn = n ^ (2 * (kq & 15));
        sAT[(4 * kq + 0) * 128 + pn] = v.x;
        sAT[(4 * kq + 1) * 128 + pn] = v.y;
        sAT[(4 * kq + 2) * 128 + pn] = v.z;
        sAT[(4 * kq + 3) * 128 + pn] = v.w;
    }
    __syncthreads();

    unsigned long long acc[4][8];
#pragma unroll
    for (int p = 0; p < 4; p++)
#pragma unroll
        for (int c = 0; c < 8; c++) acc[p][c] = 0ull;

    const unsigned long long* Wp = d_wdup + woff + tx * 8;

#pragma unroll 2
    for (int k = 0; k < K; k++) {
        const float* ar = sAT + k * 128;
        int sw = 2 * ((k >> 2) & 15);
        unsigned long long a[4];
#pragma unroll
        for (int p = 0; p < 4; p++)
            a[p] = *(const unsigned long long*)(ar + ((ty * 8 + 2 * p) ^ sw));
        ulonglong2 w01 = __ldg((const ulonglong2*)(Wp + (size_t)k * 128));
        ulonglong2 w23 = __ldg((const ulonglong2*)(Wp + (size_t)k * 128 + 2));
        ulonglong2 w45 = __ldg((const ulonglong2*)(Wp + (size_t)k * 128 + 4));
        ulonglong2 w67 = __ldg((const ulonglong2*)(Wp + (size_t)k * 128 + 6));
        unsigned long long w[8] = {w01.x, w01.y, w23.x, w23.y, w45.x, w45.y, w67.x, w67.y};
#pragma unroll
        for (int p = 0; p < 4; p++)
#pragma unroll
            for (int c = 0; c < 8; c++) fma2(acc[p][c], a[p], w[c]);
    }

    // epilogue
    int c0 = tx * 8;
    float sc[8], sh[8];
    if (BN) {
#pragma unroll
        for (int i = 0; i < 8; i++) {
            float g = __ldg(gamma + c0 + i);
            float v = __ldg(var + c0 + i);
            float m = __ldg(mean + c0 + i);
            float bt = __ldg(beta + c0 + i);
            float b = __ldg(bias + c0 + i);
            sc[i] = g * rsqrtf(v + EPSV);
            sh[i] = fmaf(b - m, sc[i], bt);
        }
    } else {
#pragma unroll
        for (int i = 0; i < 8; i++) { sc[i] = 1.0f; sh[i] = __ldg(bias + c0 + i); }
    }

#pragma unroll
    for (int p = 0; p < 4; p++) {
        float lo[8], hi[8];
#pragma unroll
        for (int c = 0; c < 8; c++) {
            unpack2(acc[p][c], lo[c], hi[c]);
            lo[c] = fmaf(lo[c], sc[c], sh[c]);
            hi[c] = fmaf(hi[c], sc[c], sh[c]);
            if (BN) { lo[c] = fmaxf(lo[c], 0.f); hi[c] = fmaxf(hi[c], 0.f); }
        }
        int r0 = nb + ty * 8 + 2 * p;
        float* o0 = d_h + (size_t)r0 * HDIM + c0;
        float* o1 = o0 + HDIM;
        *(float4*)o0 = make_float4(lo[0], lo[1], lo[2], lo[3]);
        *(float4*)(o0 + 4) = make_float4(lo[4], lo[5], lo[6], lo[7]);
        *(float4*)o1 = make_float4(hi[0], hi[1], hi[2], hi[3]);
        *(float4*)(o1 + 4) = make_float4(hi[4], hi[5], hi[6], hi[7]);
        // fp16 mirror for next gather
        __half2 hl[4], hh[4];
#pragma unroll
        for (int q = 0; q < 4; q++) {
            hl[q] = __floats2half2_rn(lo[2 * q], lo[2 * q + 1]);
            hh[q] = __floats2half2_rn(hi[2 * q], hi[2 * q + 1]);
        }
        *(uint4*)&d_h16[(size_t)r0 * HDIM + c0] = *(uint4*)hl;
        *(uint4*)&d_h16[(size_t)(r0 + 1) * HDIM + c0] = *(uint4*)hh;
    }
}

// ---------------- K7: global mean-pool (batch sorted) ----------------
__global__ __launch_bounds__(256) void pool_kernel(const int* __restrict__ batch) {
    int tx = threadIdx.x & 31;
    int ty = threadIdx.x >> 5;
    int base = blockIdx.x * 512;

    float4 acc = make_float4(0.f, 0.f, 0.f, 0.f);
    float cnt = 0.f;
    int curg = -1;

    for (int j = 0; j < 64; j++) {
        int n = base + ty + j * 8;
        int g = __ldg(batch + n);
        if (g != curg) {
            if (curg >= 0) {
                red4(d_gsum + curg * HDIM + 4 * tx, acc);
                if (tx == 0) atomicAdd(&d_gcnt[curg], cnt);
            }
            curg = g;
            acc = make_float4(0.f, 0.f, 0.f, 0.f);
            cnt = 0.f;
        }
        float4 h4 = *(const float4*)&d_h[(size_t)n * HDIM + 4 * tx];
        acc.x += h4.x; acc.y += h4.y; acc.z += h4.z; acc.w += h4.w;
        cnt += 1.f;
    }
    if (curg >= 0) {
        red4(d_gsum + curg * HDIM + 4 * tx, acc);
        if (tx == 0) atomicAdd(&d_gcnt[curg], cnt);
    }
}

// ---------------- K8: head ----------------
__global__ __launch_bounds__(128) void final_kernel(const float* __restrict__ gx,
                                                    const float* __restrict__ Wgp,
                                                    const float* __restrict__ bgp,
                                                    const float* __restrict__ Wgc,
                                                    const float* __restrict__ bgc,
                                                    float* __restrict__ out) {
    int g = blockIdx.x;
    int t = threadIdx.x;
    __shared__ float sg[HDIM];
    __shared__ float sgp[32];

    float c = fmaxf(__ldg(&d_gcnt[g]), 1.0f);
    sg[t] = d_gsum[g * HDIM + t] / c;
    if (t < 32) {
        float acc = __ldg(bgp + t);
        for (int d = 0; d < 6; d++)
            acc = fmaf(__ldg(gx + g * 6 + d), __ldg(Wgp + d * 32 + t), acc);
        sgp[t] = fmaxf(acc, 0.f);
    }
    __syncthreads();

    float acc = __ldg(bgc + t);
#pragma unroll 4
    for (int k = 0; k < HDIM; k++)
        acc = fmaf(sg[k], __ldg(Wgc + (size_t)k * HDIM + t), acc);
#pragma unroll 4
    for (int k = 0; k < 32; k++)
        acc = fmaf(sgp[k], __ldg(Wgc + (size_t)(HDIM + k) * HDIM + t), acc);
    out[g * HDIM + t] = acc;
}

// ---------------- launch ----------------
extern "C" void kernel_launch(void* const* d_in, const int* in_sizes, int n_in,
                              void* d_out, int out_size) {
    const float* x       = (const float*)d_in[0];
    const float* eattr   = (const float*)d_in[1];
    const float* gx      = (const float*)d_in[2];
    const float* W_in    = (const float*)d_in[3];
    const float* b_in    = (const float*)d_in[4];
    const float* W_edge  = (const float*)d_in[5];
    const float* b_edge  = (const float*)d_in[6];
    const float* W_gcn   = (const float*)d_in[7];
    const float* b_gcn   = (const float*)d_in[8];
    const float* bn_g    = (const float*)d_in[9];
    const float* bn_b    = (const float*)d_in[10];
    const float* bn_m    = (const float*)d_in[11];
    const float* bn_v    = (const float*)d_in[12];
    const float* W_gproj = (const float*)d_in[13];
    const float* b_gproj = (const float*)d_in[14];
    const float* W_gcomb = (const float*)d_in[15];
    const float* b_gcomb = (const float*)d_in[16];
    const int*   row     = (const int*)d_in[17];
    const int*   col     = (const int*)d_in[18];
    const int*   batch   = (const int*)d_in[19];
    float* out = (float*)d_out;

    cudaFuncSetAttribute(gemm_kernel<HDIM, true>,
                         cudaFuncAttributeMaxDynamicSharedMemorySize, HDIM * 128 * 4);
    cudaFuncSetAttribute(gemm_kernel<DIN, false>,
                         cudaFuncAttributeMaxDynamicSharedMemorySize, DIN * 128 * 4);

    zero_kernel<<<512, 256>>>();
    deg_kernel<<<N_EDGES / 256, 256>>>(row);
    scanA_kernel<<<128, 256>>>();
    scanB_kernel<<<1, 128>>>();
    scanC_kernel<<<128, 256>>>();
    build_kernel<<<N_EDGES / 256, 256>>>(row, col, eattr);
    wdup_kernel<<<(DIN + 3 * HDIM) * HDIM / 256, 256>>>(W_in, W_gcn);

    gemm_kernel<DIN, false><<<N_NODES / 128, 256, DIN * 128 * 4>>>(
        x, 0, b_in, nullptr, nullptr, nullptr, nullptr);

    for (int l = 0; l < 3; l++) {
        gather_kernel<<<N_NODES / 8, 256>>>(W_edge, b_edge);
        gemm_kernel<HDIM, true><<<N_NODES / 128, 256, HDIM * 128 * 4>>>(
            nullptr, DIN * HDIM + l * HDIM * HDIM, b_gcn + l * HDIM,
            bn_g + l * HDIM, bn_b + l * HDIM, bn_m + l * HDIM, bn_v + l * HDIM);
    }

    pool_kernel<<<N_NODES / 512, 256>>>(batch);
    final_kernel<<<N_GRAPHS, HDIM>>>(gx, W_gproj, b_gproj, W_gcomb, b_gcomb, out);
}

// round 5
// speedup vs baseline: 1.7445x; 1.4241x over previous
#include <cuda_runtime.h>
#include <cuda_fp16.h>
#include <cuda_bf16.h>
#include <cstdint>

#define N_NODES 131072
#define N_EDGES 2097152
#define N_GRAPHS 64
#define DIN 64
#define HDIM 128
#define EPSV 1e-5f

// ---------------- scratch (device globals: allocation-free) ----------------
__device__ __align__(128) float  d_h[(size_t)N_NODES * HDIM];    // 64 MB
__device__ __align__(128) __half d_h16[(size_t)N_NODES * HDIM];  // 32 MB gather table
__device__ __align__(128) float  d_t[(size_t)N_NODES * HDIM];    // 64 MB (streamed)
__device__ __align__(128) int    d_colp[N_EDGES];
__device__ __align__(128) float2 d_eap[N_EDGES];
__device__ __align__(128) int    d_degi[N_NODES];
__device__ __align__(128) int    d_cnt[N_NODES];
__device__ __align__(128) int    d_start[N_NODES + 1];
__device__ __align__(128) float  d_inv[N_NODES];
__device__ __align__(128) int    d_bsum[128];
__device__ __align__(128) int    d_bbase[128];
__device__ __align__(128) unsigned long long d_wdup[DIN * HDIM];
// per-thread MMA B-fragments: [layer][hi/lo][kstep 8][ntile 16][lane 32][reg 2] u32
__device__ __align__(128) uint32_t d_wfrag[3 * 2 * 8 * 16 * 32 * 2];
__device__ __align__(128) float  d_gsum[N_GRAPHS * HDIM];
__device__ __align__(128) float  d_gcnt[N_GRAPHS];

// ---------------- helpers ----------------
__device__ __forceinline__ void fma2(unsigned long long& d, unsigned long long a, unsigned long long b) {
    asm("fma.rn.f32x2 %0, %1, %2, %0;" : "+l"(d) : "l"(a), "l"(b));
}
__device__ __forceinline__ unsigned long long pack2(float a) {
    unsigned long long r;
    asm("mov.b64 %0, {%1, %1};" : "=l"(r) : "f"(a));
    return r;
}
__device__ __forceinline__ void unpack2(unsigned long long v, float& lo, float& hi) {
    asm("mov.b64 {%0, %1}, %2;" : "=f"(lo), "=f"(hi) : "l"(v));
}
__device__ __forceinline__ void red4(float* p, float4 v) {
    asm volatile("red.global.add.v4.f32 [%0], {%1,%2,%3,%4};"
                 :: "l"(p), "f"(v.x), "f"(v.y), "f"(v.z), "f"(v.w) : "memory");
}
__device__ __forceinline__ float4 ld_h16(int c, int lane) {
    uint2 u = __ldg((const uint2*)(d_h16 + (size_t)c * HDIM) + lane);
    __half2* p = (__half2*)&u;
    float2 f0 = __half22float2(p[0]);
    float2 f1 = __half22float2(p[1]);
    return make_float4(f0.x, f0.y, f1.x, f1.y);
}
__device__ __forceinline__ void mma_bf16(float* d, uint32_t a0, uint32_t a1, uint32_t a2,
                                         uint32_t a3, uint32_t b0, uint32_t b1) {
    asm volatile(
        "mma.sync.aligned.m16n8k16.row.col.f32.bf16.bf16.f32 "
        "{%0,%1,%2,%3}, {%4,%5,%6,%7}, {%8,%9}, {%0,%1,%2,%3};"
        : "+f"(d[0]), "+f"(d[1]), "+f"(d[2]), "+f"(d[3])
        : "r"(a0), "r"(a1), "r"(a2), "r"(a3), "r"(b0), "r"(b1));
}

// ---------------- K0: zero counters ----------------
__global__ void zero_kernel() {
    int i = blockIdx.x * blockDim.x + threadIdx.x;
    if (i < N_NODES) { d_degi[i] = 0; d_cnt[i] = 0; }
    if (i < N_GRAPHS * HDIM) d_gsum[i] = 0.0f;
    if (i < N_GRAPHS) d_gcnt[i] = 0.0f;
}

// ---------------- K1: degree count ----------------
__global__ void deg_kernel(const int* __restrict__ row) {
    int e = blockIdx.x * blockDim.x + threadIdx.x;
    atomicAdd(&d_degi[row[e]], 1);
}

// ---------------- K2a/b/c: exclusive scan of deg ----------------
__global__ __launch_bounds__(256) void scanA_kernel() {
    __shared__ int sp[256];
    int tid = threadIdx.x;
    int4 dv = ((const int4*)d_degi)[blockIdx.x * 256 + tid];
    int s = dv.x + dv.y + dv.z + dv.w;
    sp[tid] = s;
    __syncthreads();
    for (int off = 128; off > 0; off >>= 1) {
        if (tid < off) sp[tid] += sp[tid + off];
        __syncthreads();
    }
    if (tid == 0) d_bsum[blockIdx.x] = sp[0];
}

__global__ __launch_bounds__(128) void scanB_kernel() {
    __shared__ int sp[128];
    int tid = threadIdx.x;
    int s = d_bsum[tid];
    sp[tid] = s;
    __syncthreads();
    for (int off = 1; off < 128; off <<= 1) {
        int v = (tid >= off) ? sp[tid - off] : 0;
        __syncthreads();
        sp[tid] += v;
        __syncthreads();
    }
    d_bbase[tid] = sp[tid] - s;
    if (tid == 127) d_start[N_NODES] = sp[127];
}

__global__ __launch_bounds__(256) void scanC_kernel() {
    __shared__ int sp[256];
    int tid = threadIdx.x;
    int idx = blockIdx.x * 256 + tid;
    int4 dv = ((const int4*)d_degi)[idx];
    int s = dv.x + dv.y + dv.z + dv.w;
    sp[tid] = s;
    __syncthreads();
    for (int off = 1; off < 256; off <<= 1) {
        int v = (tid >= off) ? sp[tid - off] : 0;
        __syncthreads();
        sp[tid] += v;
        __syncthreads();
    }
    int base = d_bbase[blockIdx.x] + sp[tid] - s;
    int4 st;
    st.x = base;
    st.y = base + dv.x;
    st.z = st.y + dv.y;
    st.w = st.z + dv.z;
    ((int4*)d_start)[idx] = st;
    float4 iv;
    iv.x = 1.0f / (float)max(dv.x, 1);
    iv.y = 1.0f / (float)max(dv.y, 1);
    iv.z = 1.0f / (float)max(dv.z, 1);
    iv.w = 1.0f / (float)max(dv.w, 1);
    ((float4*)d_inv)[idx] = iv;
}

// ---------------- K3: counting-sort edges into CSR order ----------------
__global__ __launch_bounds__(256) void build_kernel(const int* __restrict__ row,
                                                    const int* __restrict__ col,
                                                    const float* __restrict__ eattr) {
    int e = blockIdx.x * blockDim.x + threadIdx.x;
    int r = __ldg(row + e);
    int pos = __ldg(d_start + r) + atomicAdd(&d_cnt[r], 1);
    d_colp[pos] = __ldg(col + e);
    d_eap[pos] = __ldg((const float2*)eattr + e);
}

// ---------------- K4a: dup-pack input weights (fma2 path) ----------------
__global__ __launch_bounds__(256) void wdup_kernel(const float* __restrict__ Win) {
    int i = blockIdx.x * blockDim.x + threadIdx.x;
    d_wdup[i] = pack2(__ldg(Win + i));
}

// ---------------- K4b: build per-thread MMA B-fragments (W hi/lo bf16) ----------------
// frag mapping (m16n8k16 col B): k = ks*16 + tg*2 + q + r*8 ; n = nt*8 + (lane>>2)
__global__ __launch_bounds__(256) void wfrag_kernel(const float* __restrict__ Wg) {
    int i = blockIdx.x * blockDim.x + threadIdx.x;  // < 49152
    int r = i & 1;
    int lane = (i >> 1) & 31;
    int nt = (i >> 6) & 15;
    int ks = (i >> 10) & 7;
    int s = (i >> 13) & 1;
    int l = i >> 14;
    int tg = lane & 3;
    int g = lane >> 2;
    int k0 = ks * 16 + tg * 2 + r * 8;
    int n = nt * 8 + g;
    float w0 = __ldg(Wg + (size_t)l * HDIM * HDIM + k0 * HDIM + n);
    float w1 = __ldg(Wg + (size_t)l * HDIM * HDIM + (k0 + 1) * HDIM + n);
    __nv_bfloat16 v0, v1;
    if (s == 0) {
        v0 = __float2bfloat16(w0);
        v1 = __float2bfloat16(w1);
    } else {
        v0 = __float2bfloat16(w0 - __bfloat162float(__float2bfloat16(w0)));
        v1 = __float2bfloat16(w1 - __bfloat162float(__float2bfloat16(w1)));
    }
    uint32_t u = (uint32_t)*(uint16_t*)&v0 | ((uint32_t)*(uint16_t*)&v1 << 16);
    d_wfrag[i] = u;
}

// ---------------- K5: CSR gather ----------------
__global__ __launch_bounds__(256) void gather_kernel(const float* __restrict__ We,
                                                     const float* __restrict__ be) {
    int lane = threadIdx.x & 31;
    int n = blockIdx.x * 8 + (threadIdx.x >> 5);

    float4 w0 = __ldg((const float4*)We + lane);
    float4 w1 = __ldg((const float4*)(We + HDIM) + lane);
    float4 bb = __ldg((const float4*)be + lane);

    int js = __ldg(d_start + n);
    int je = __ldg(d_start + n + 1);

    float4 acc = make_float4(0.f, 0.f, 0.f, 0.f);

    int j = js;
    for (; j + 4 <= je; j += 4) {
        int c0 = __ldg(d_colp + j);
        int c1 = __ldg(d_colp + j + 1);
        int c2 = __ldg(d_colp + j + 2);
        int c3 = __ldg(d_colp + j + 3);
        float2 a0 = __ldg(d_eap + j);
        float2 a1 = __ldg(d_eap + j + 1);
        float2 a2 = __ldg(d_eap + j + 2);
        float2 a3 = __ldg(d_eap + j + 3);
        float4 v0 = ld_h16(c0, lane);
        float4 v1 = ld_h16(c1, lane);
        float4 v2 = ld_h16(c2, lane);
        float4 v3 = ld_h16(c3, lane);
#define EDGE(v, a)                                                    \
        {                                                             \
            float4 e;                                                 \
            e.x = fmaf(a.x, w0.x, fmaf(a.y, w1.x, bb.x));             \
            e.y = fmaf(a.x, w0.y, fmaf(a.y, w1.y, bb.y));             \
            e.z = fmaf(a.x, w0.z, fmaf(a.y, w1.z, bb.z));             \
            e.w = fmaf(a.x, w0.w, fmaf(a.y, w1.w, bb.w));             \
            acc.x = fmaf(v.x, e.x, acc.x);                            \
            acc.y = fmaf(v.y, e.y, acc.y);                            \
            acc.z = fmaf(v.z, e.z, acc.z);                            \
            acc.w = fmaf(v.w, e.w, acc.w);                            \
        }
        EDGE(v0, a0) EDGE(v1, a1) EDGE(v2, a2) EDGE(v3, a3)
    }
    for (; j < je; j++) {
        int c0 = __ldg(d_colp + j);
        float2 a0 = __ldg(d_eap + j);
        float4 v0 = ld_h16(c0, lane);
        EDGE(v0, a0)
    }
#undef EDGE

    float inv = __ldg(d_inv + n);
    float4 hv = __ldg((const float4*)(d_h + (size_t)n * HDIM) + lane);
    float4 t;
    t.x = fmaf(acc.x, inv, hv.x);
    t.y = fmaf(acc.y, inv, hv.y);
    t.z = fmaf(acc.z, inv, hv.z);
    t.w = fmaf(acc.w, inv, hv.w);
    __stcs((float4*)(d_t + (size_t)n * HDIM) + lane, t);
}

// ---------------- K6: input GEMM (fma2, fp32 exact): h = x @ W_in + b ----------------
__global__ __launch_bounds__(256) void ingemm_kernel(const float* __restrict__ Ax,
                                                     const float* __restrict__ bias) {
    extern __shared__ float sAT[];  // [64][128] swizzled
    const int tid = threadIdx.x;
    const int tx = tid & 15;
    const int ty = tid >> 4;
    const int nb = blockIdx.x * 128;
    constexpr int K = DIN;
    constexpr int KQ = K / 4;

#pragma unroll
    for (int j = 0; j < K / 8; j++) {
        int q = tid + 256 * j;
        int n = q / KQ;
        int kq = q % KQ;
        float4 v = __ldcs((const float4*)&Ax[(size_t)(nb + n) * K + 4 * kq]);
        int pn = n ^ (2 * (kq & 15));
        sAT[(4 * kq + 0) * 128 + pn] = v.x;
        sAT[(4 * kq + 1) * 128 + pn] = v.y;
        sAT[(4 * kq + 2) * 128 + pn] = v.z;
        sAT[(4 * kq + 3) * 128 + pn] = v.w;
    }
    __syncthreads();

    unsigned long long acc[4][8];
#pragma unroll
    for (int p = 0; p < 4; p++)
#pragma unroll
        for (int c = 0; c < 8; c++) acc[p][c] = 0ull;

    const unsigned long long* Wp = d_wdup + tx * 8;

#pragma unroll 2
    for (int k = 0; k < K; k++) {
        const float* ar = sAT + k * 128;
        int sw = 2 * ((k >> 2) & 15);
        unsigned long long a[4];
#pragma unroll
        for (int p = 0; p < 4; p++)
            a[p] = *(const unsigned long long*)(ar + ((ty * 8 + 2 * p) ^ sw));
        ulonglong2 w01 = __ldg((const ulonglong2*)(Wp + (size_t)k * 128));
        ulonglong2 w23 = __ldg((const ulonglong2*)(Wp + (size_t)k * 128 + 2));
        ulonglong2 w45 = __ldg((const ulonglong2*)(Wp + (size_t)k * 128 + 4));
        ulonglong2 w67 = __ldg((const ulonglong2*)(Wp + (size_t)k * 128 + 6));
        unsigned long long w[8] = {w01.x, w01.y, w23.x, w23.y, w45.x, w45.y, w67.x, w67.y};
#pragma unroll
        for (int p = 0; p < 4; p++)
#pragma unroll
            for (int c = 0; c < 8; c++) fma2(acc[p][c], a[p], w[c]);
    }

    int c0 = tx * 8;
#pragma unroll
    for (int p = 0; p < 4; p++) {
        float lo[8], hi[8];
#pragma unroll
        for (int c = 0; c < 8; c++) {
            unpack2(acc[p][c], lo[c], hi[c]);
            lo[c] += __ldg(bias + c0 + c);
            hi[c] += __ldg(bias + c0 + c);
        }
        int r0 = nb + ty * 8 + 2 * p;
        float* o0 = d_h + (size_t)r0 * HDIM + c0;
        float* o1 = o0 + HDIM;
        *(float4*)o0 = make_float4(lo[0], lo[1], lo[2], lo[3]);
        *(float4*)(o0 + 4) = make_float4(lo[4], lo[5], lo[6], lo[7]);
        *(float4*)o1 = make_float4(hi[0], hi[1], hi[2], hi[3]);
        *(float4*)(o1 + 4) = make_float4(hi[4], hi[5], hi[6], hi[7]);
        __half2 hl[4], hh[4];
#pragma unroll
        for (int q = 0; q < 4; q++) {
            hl[q] = __floats2half2_rn(lo[2 * q], lo[2 * q + 1]);
            hh[q] = __floats2half2_rn(hi[2 * q], hi[2 * q + 1]);
        }
        *(uint4*)&d_h16[(size_t)r0 * HDIM + c0] = *(uint4*)hl;
        *(uint4*)&d_h16[(size_t)(r0 + 1) * HDIM + c0] = *(uint4*)hh;
    }
}

// ---------------- K7: mma.sync layer GEMM: h = relu(BN(t @ (Whi+Wlo) + b)) ----------------
// 256 thr = 8 warps, 128 nodes/block, each warp: 16 rows x 128 cols.
#define SM_A_BYTES 34816                      // [128][136] bf16
#define SM_B_BYTES 65536                      // [2][8][16][32][2] u32
#define SM_TOT (SM_A_BYTES + SM_B_BYTES + 1024)
__global__ __launch_bounds__(256) void mmagemm_kernel(int layer,
                                                      const float* __restrict__ bias,
                                                      const float* __restrict__ gamma,
                                                      const float* __restrict__ beta,
                                                      const float* __restrict__ mean,
                                                      const float* __restrict__ var) {
    extern __shared__ char smem[];
    __nv_bfloat16* sA = (__nv_bfloat16*)smem;                 // stride 136
    uint32_t* sB = (uint32_t*)(smem + SM_A_BYTES);
    float* sBN = (float*)(smem + SM_A_BYTES + SM_B_BYTES);    // sc[128], sh[128]

    const int tid = threadIdx.x;
    const int lane = tid & 31;
    const int wid = tid >> 5;
    const int nb = blockIdx.x * 128;

    // BN scale/shift
    if (tid < 128) {
        float g = __ldg(gamma + tid);
        float v = __ldg(var + tid);
        float m = __ldg(mean + tid);
        float bt = __ldg(beta + tid);
        float b = __ldg(bias + tid);
        float sc = g * rsqrtf(v + EPSV);
        sBN[tid] = sc;
        sBN[128 + tid] = fmaf(b - m, sc, bt);
    }

    // stage A: 128x128 f32 -> bf16 [128][136]
    const float4* T = (const float4*)(d_t + (size_t)nb * HDIM);
#pragma unroll
    for (int i = 0; i < 16; i++) {
        int q = tid + 256 * i;           // 0..4095
        int m = q >> 5, c0 = (q & 31) * 4;
        float4 v = __ldcs(T + q);
        __nv_bfloat162 p0 = __floats2bfloat162_rn(v.x, v.y);
        __nv_bfloat162 p1 = __floats2bfloat162_rn(v.z, v.w);
        *(uint2*)(sA + m * 136 + c0) = make_uint2(*(uint32_t*)&p0, *(uint32_t*)&p1);
    }
    // stage B frags (hi+lo, 64 KB)
    const uint4* BF = (const uint4*)(d_wfrag + layer * 16384);
#pragma unroll
    for (int i = 0; i < 16; i++) {
        int q = tid + 256 * i;           // 0..4095
        ((uint4*)sB)[q] = __ldg(BF + q);
    }
    __syncthreads();

    const int g = lane >> 2, tg = lane & 3;
    float acc[16][4];
#pragma unroll
    for (int nt = 0; nt < 16; nt++)
#pragma unroll
        for (int c = 0; c < 4; c++) acc[nt][c] = 0.f;

    const __nv_bfloat16* ar0 = sA + (wid * 16 + g) * 136;
    const __nv_bfloat16* ar1 = ar0 + 8 * 136;

#pragma unroll
    for (int ks = 0; ks < 8; ks++) {
        int k0 = ks * 16 + tg * 2;
        uint32_t a0 = *(const uint32_t*)(ar0 + k0);
        uint32_t a1 = *(const uint32_t*)(ar1 + k0);
        uint32_t a2 = *(const uint32_t*)(ar0 + k0 + 8);
        uint32_t a3 = *(const uint32_t*)(ar1 + k0 + 8);
        const uint32_t* bh = sB + (ks * 16) * 64 + lane * 2;
        const uint32_t* bl = bh + 8 * 16 * 64;
#pragma unroll
        for (int nt = 0; nt < 16; nt++) {
            uint2 bhv = *(const uint2*)(bh + nt * 64);
            uint2 blv = *(const uint2*)(bl + nt * 64);
            mma_bf16(acc[nt], a0, a1, a2, a3, bhv.x, bhv.y);
            mma_bf16(acc[nt], a0, a1, a2, a3, blv.x, blv.y);
        }
    }

    // epilogue: BN + ReLU, write d_h (f32) and d_h16 mirror
    int r0 = nb + wid * 16 + g;
    float* oh0 = d_h + (size_t)r0 * HDIM;
    float* oh1 = oh0 + 8 * HDIM;
    __half* om0 = d_h16 + (size_t)r0 * HDIM;
    __half* om1 = om0 + 8 * HDIM;
#pragma unroll
    for (int nt = 0; nt < 16; nt++) {
        int c = nt * 8 + tg * 2;
        float sc0 = sBN[c], sc1 = sBN[c + 1];
        float sh0 = sBN[128 + c], sh1 = sBN[128 + c + 1];
        float o00 = fmaxf(fmaf(acc[nt][0], sc0, sh0), 0.f);
        float o01 = fmaxf(fmaf(acc[nt][1], sc1, sh1), 0.f);
        float o10 = fmaxf(fmaf(acc[nt][2], sc0, sh0), 0.f);
        float o11 = fmaxf(fmaf(acc[nt][3], sc1, sh1), 0.f);
        *(float2*)(oh0 + c) = make_float2(o00, o01);
        *(float2*)(oh1 + c) = make_float2(o10, o11);
        __half2 m0 = __floats2half2_rn(o00, o01);
        __half2 m1 = __floats2half2_rn(o10, o11);
        *(__half2*)(om0 + c) = m0;
        *(__half2*)(om1 + c) = m1;
    }
}

// ---------------- K8: global mean-pool (batch sorted) ----------------
__global__ __launch_bounds__(256) void pool_kernel(const int* __restrict__ batch) {
    int tx = threadIdx.x & 31;
    int ty = threadIdx.x >> 5;
    int base = blockIdx.x * 512;

    float4 acc = make_float4(0.f, 0.f, 0.f, 0.f);
    float cnt = 0.f;
    int curg = -1;

    for (int j = 0; j < 64; j++) {
        int n = base + ty + j * 8;
        int g = __ldg(batch + n);
        if (g != curg) {
            if (curg >= 0) {
                red4(d_gsum + curg * HDIM + 4 * tx, acc);
                if (tx == 0) atomicAdd(&d_gcnt[curg], cnt);
            }
            curg = g;
            acc = make_float4(0.f, 0.f, 0.f, 0.f);
            cnt = 0.f;
        }
        float4 h4 = *(const float4*)&d_h[(size_t)n * HDIM + 4 * tx];
        acc.x += h4.x; acc.y += h4.y; acc.z += h4.z; acc.w += h4.w;
        cnt += 1.f;
    }
    if (curg >= 0) {
        red4(d_gsum + curg * HDIM + 4 * tx, acc);
        if (tx == 0) atomicAdd(&d_gcnt[curg], cnt);
    }
}

// ---------------- K9: head ----------------
__global__ __launch_bounds__(128) void final_kernel(const float* __restrict__ gx,
                                                    const float* __restrict__ Wgp,
                                                    const float* __restrict__ bgp,
                                                    const float* __restrict__ Wgc,
                                                    const float* __restrict__ bgc,
                                                    float* __restrict__ out) {
    int g = blockIdx.x;
    int t = threadIdx.x;
    __shared__ float sg[HDIM];
    __shared__ float sgp[32];

    float c = fmaxf(__ldg(&d_gcnt[g]), 1.0f);
    sg[t] = d_gsum[g * HDIM + t] / c;
    if (t < 32) {
        float acc = __ldg(bgp + t);
        for (int d = 0; d < 6; d++)
            acc = fmaf(__ldg(gx + g * 6 + d), __ldg(Wgp + d * 32 + t), acc);
        sgp[t] = fmaxf(acc, 0.f);
    }
    __syncthreads();

    float acc = __ldg(bgc + t);
#pragma unroll 4
    for (int k = 0; k < HDIM; k++)
        acc = fmaf(sg[k], __ldg(Wgc + (size_t)k * HDIM + t), acc);
#pragma unroll 4
    for (int k = 0; k < 32; k++)
        acc = fmaf(sgp[k], __ldg(Wgc + (size_t)(HDIM + k) * HDIM + t), acc);
    out[g * HDIM + t] = acc;
}

// ---------------- launch ----------------
extern "C" void kernel_launch(void* const* d_in, const int* in_sizes, int n_in,
                              void* d_out, int out_size) {
    const float* x       = (const float*)d_in[0];
    const float* eattr   = (const float*)d_in[1];
    const float* gx      = (const float*)d_in[2];
    const float* W_in    = (const float*)d_in[3];
    const float* b_in    = (const float*)d_in[4];
    const float* W_edge  = (const float*)d_in[5];
    const float* b_edge  = (const float*)d_in[6];
    const float* W_gcn   = (const float*)d_in[7];
    const float* b_gcn   = (const float*)d_in[8];
    const float* bn_g    = (const float*)d_in[9];
    const float* bn_b    = (const float*)d_in[10];
    const float* bn_m    = (const float*)d_in[11];
    const float* bn_v    = (const float*)d_in[12];
    const float* W_gproj = (const float*)d_in[13];
    const float* b_gproj = (const float*)d_in[14];
    const float* W_gcomb = (const float*)d_in[15];
    const float* b_gcomb = (const float*)d_in[16];
    const int*   row     = (const int*)d_in[17];
    const int*   col     = (const int*)d_in[18];
    const int*   batch   = (const int*)d_in[19];
    float* out = (float*)d_out;

    cudaFuncSetAttribute(ingemm_kernel, cudaFuncAttributeMaxDynamicSharedMemorySize,
                         DIN * 128 * 4);
    cudaFuncSetAttribute(mmagemm_kernel, cudaFuncAttributeMaxDynamicSharedMemorySize,
                         SM_TOT);

    zero_kernel<<<512, 256>>>();
    deg_kernel<<<N_EDGES / 256, 256>>>(row);
    scanA_kernel<<<128, 256>>>();
    scanB_kernel<<<1, 128>>>();
    scanC_kernel<<<128, 256>>>();
    build_kernel<<<N_EDGES / 256, 256>>>(row, col, eattr);
    wdup_kernel<<<DIN * HDIM / 256, 256>>>(W_in);
    wfrag_kernel<<<192, 256>>>(W_gcn);

    ingemm_kernel<<<N_NODES / 128, 256, DIN * 128 * 4>>>(x, b_in);

    for (int l = 0; l < 3; l++) {
        gather_kernel<<<N_NODES / 8, 256>>>(W_edge, b_edge);
        mmagemm_kernel<<<N_NODES / 128, 256, SM_TOT>>>(
            l, b_gcn + l * HDIM,
            bn_g + l * HDIM, bn_b + l * HDIM, bn_m + l * HDIM, bn_v + l * HDIM);
    }

    pool_kernel<<<N_NODES / 512, 256>>>(batch);
    final_kernel<<<N_GRAPHS, HDIM>>>(gx, W_gproj, b_gproj, W_gcomb, b_gcomb, out);
}

// round 6
// speedup vs baseline: 2.8524x; 1.6351x over previous
#include <cuda_runtime.h>
#include <cuda_fp16.h>
#include <cuda_bf16.h>
#include <cstdint>

#define N_NODES 131072
#define N_EDGES 2097152
#define E_PAD   (N_EDGES + 8 * N_NODES)   // 3145728 padded CSR slots
#define N_GRAPHS 64
#define DIN 64
#define HDIM 128
#define EPSV 1e-5f

// ---------------- scratch (device globals: allocation-free) ----------------
__device__ __align__(128) __half d_h16[((size_t)N_NODES + 1) * HDIM];  // 32 MB + sentinel row
__device__ __align__(128) __nv_bfloat16 d_t16[(size_t)N_NODES * HDIM]; // 32 MB
__device__ __align__(128) uint2  d_edge[E_PAD];                        // {col, half2 attr} 24 MB
__device__ __align__(128) int    d_degi[N_NODES];
__device__ __align__(128) int    d_cnt[N_NODES];
__device__ __align__(128) int    d_start[N_NODES + 1];
__device__ __align__(128) float  d_inv[N_NODES];
__device__ __align__(128) int    d_bsum[128];
__device__ __align__(128) int    d_bbase[128];
__device__ __align__(128) unsigned long long d_wdup[DIN * HDIM];
// per-thread MMA B-fragments: [layer][hi/lo][kstep 8][ntile 16][lane 32][reg 2]
__device__ __align__(128) uint32_t d_wfrag[3 * 2 * 8 * 16 * 32 * 2];
__device__ __align__(128) float  d_gsum[N_GRAPHS * HDIM];
__device__ __align__(128) float  d_gcnt[N_GRAPHS];

// ---------------- helpers ----------------
__device__ __forceinline__ void fma2(unsigned long long& d, unsigned long long a, unsigned long long b) {
    asm("fma.rn.f32x2 %0, %1, %2, %0;" : "+l"(d) : "l"(a), "l"(b));
}
__device__ __forceinline__ unsigned long long pack2(float a) {
    unsigned long long r;
    asm("mov.b64 %0, {%1, %1};" : "=l"(r) : "f"(a));
    return r;
}
__device__ __forceinline__ void unpack2(unsigned long long v, float& lo, float& hi) {
    asm("mov.b64 {%0, %1}, %2;" : "=f"(lo), "=f"(hi) : "l"(v));
}
__device__ __forceinline__ void red4(float* p, float4 v) {
    asm volatile("red.global.add.v4.f32 [%0], {%1,%2,%3,%4};"
                 :: "l"(p), "f"(v.x), "f"(v.y), "f"(v.z), "f"(v.w) : "memory");
}
__device__ __forceinline__ float4 h16_to_f4(uint2 u) {
    __half2* p = (__half2*)&u;
    float2 f0 = __half22float2(p[0]);
    float2 f1 = __half22float2(p[1]);
    return make_float4(f0.x, f0.y, f1.x, f1.y);
}
__device__ __forceinline__ void mma_bf16(float* d, uint32_t a0, uint32_t a1, uint32_t a2,
                                         uint32_t a3, uint32_t b0, uint32_t b1) {
    asm volatile(
        "mma.sync.aligned.m16n8k16.row.col.f32.bf16.bf16.f32 "
        "{%0,%1,%2,%3}, {%4,%5,%6,%7}, {%8,%9}, {%0,%1,%2,%3};"
        : "+f"(d[0]), "+f"(d[1]), "+f"(d[2]), "+f"(d[3])
        : "r"(a0), "r"(a1), "r"(a2), "r"(a3), "r"(b0), "r"(b1));
}

// ---------------- K0: zero counters + sentinel h16 row ----------------
__global__ void zero_kernel() {
    int i = blockIdx.x * blockDim.x + threadIdx.x;
    if (i < N_NODES) { d_degi[i] = 0; d_cnt[i] = 0; }
    if (i < N_GRAPHS * HDIM) d_gsum[i] = 0.0f;
    if (i < N_GRAPHS) d_gcnt[i] = 0.0f;
    if (i < 16) ((uint4*)(d_h16 + (size_t)N_NODES * HDIM))[i] = make_uint4(0, 0, 0, 0);
}

// ---------------- K0b: fill edge table with sentinel records ----------------
__global__ void fill_kernel() {
    int i = blockIdx.x * blockDim.x + threadIdx.x;
    d_edge[i] = make_uint2((uint32_t)N_NODES, 0u);
}

// ---------------- K1: degree count ----------------
__global__ void deg_kernel(const int* __restrict__ row) {
    int e = blockIdx.x * blockDim.x + threadIdx.x;
    atomicAdd(&d_degi[row[e]], 1);
}

// ---------------- K2a/b/c: exclusive scan of PADDED deg ----------------
__global__ __launch_bounds__(256) void scanA_kernel() {
    __shared__ int sp[256];
    int tid = threadIdx.x;
    int4 dv = ((const int4*)d_degi)[blockIdx.x * 256 + tid];
    int s = ((dv.x + 7) & ~7) + ((dv.y + 7) & ~7) + ((dv.z + 7) & ~7) + ((dv.w + 7) & ~7);
    sp[tid] = s;
    __syncthreads();
    for (int off = 128; off > 0; off >>= 1) {
        if (tid < off) sp[tid] += sp[tid + off];
        __syncthreads();
    }
    if (tid == 0) d_bsum[blockIdx.x] = sp[0];
}

__global__ __launch_bounds__(128) void scanB_kernel() {
    __shared__ int sp[128];
    int tid = threadIdx.x;
    int s = d_bsum[tid];
    sp[tid] = s;
    __syncthreads();
    for (int off = 1; off < 128; off <<= 1) {
        int v = (tid >= off) ? sp[tid - off] : 0;
        __syncthreads();
        sp[tid] += v;
        __syncthreads();
    }
    d_bbase[tid] = sp[tid] - s;
    if (tid == 127) d_start[N_NODES] = sp[127];
}

__global__ __launch_bounds__(256) void scanC_kernel() {
    __shared__ int sp[256];
    int tid = threadIdx.x;
    int idx = blockIdx.x * 256 + tid;
    int4 dv = ((const int4*)d_degi)[idx];
    int p0 = (dv.x + 7) & ~7, p1 = (dv.y + 7) & ~7, p2 = (dv.z + 7) & ~7, p3 = (dv.w + 7) & ~7;
    int s = p0 + p1 + p2 + p3;
    sp[tid] = s;
    __syncthreads();
    for (int off = 1; off < 256; off <<= 1) {
        int v = (tid >= off) ? sp[tid - off] : 0;
        __syncthreads();
        sp[tid] += v;
        __syncthreads();
    }
    int base = d_bbase[blockIdx.x] + sp[tid] - s;
    int4 st;
    st.x = base;
    st.y = base + p0;
    st.z = st.y + p1;
    st.w = st.z + p2;
    ((int4*)d_start)[idx] = st;
    float4 iv;
    iv.x = 1.0f / (float)max(dv.x, 1);
    iv.y = 1.0f / (float)max(dv.y, 1);
    iv.z = 1.0f / (float)max(dv.z, 1);
    iv.w = 1.0f / (float)max(dv.w, 1);
    ((float4*)d_inv)[idx] = iv;
}

// ---------------- K3: counting-sort edges into padded CSR ----------------
__global__ __launch_bounds__(256) void build_kernel(const int* __restrict__ row,
                                                    const int* __restrict__ col,
                                                    const float* __restrict__ eattr) {
    int e = blockIdx.x * blockDim.x + threadIdx.x;
    int r = __ldg(row + e);
    int pos = __ldg(d_start + r) + atomicAdd(&d_cnt[r], 1);
    float2 a = __ldg((const float2*)eattr + e);
    __half2 ah = __floats2half2_rn(a.x, a.y);
    d_edge[pos] = make_uint2((uint32_t)__ldg(col + e), *(uint32_t*)&ah);
}

// ---------------- K4a: dup-pack input weights ----------------
__global__ __launch_bounds__(256) void wdup_kernel(const float* __restrict__ Win) {
    int i = blockIdx.x * blockDim.x + threadIdx.x;
    d_wdup[i] = pack2(__ldg(Win + i));
}

// ---------------- K4b: per-thread MMA B-fragments (W hi/lo bf16) ----------------
__global__ __launch_bounds__(256) void wfrag_kernel(const float* __restrict__ Wg) {
    int i = blockIdx.x * blockDim.x + threadIdx.x;  // < 49152
    int r = i & 1;
    int lane = (i >> 1) & 31;
    int nt = (i >> 6) & 15;
    int ks = (i >> 10) & 7;
    int s = (i >> 13) & 1;
    int l = i >> 14;
    int tg = lane & 3;
    int g = lane >> 2;
    int k0 = ks * 16 + tg * 2 + r * 8;
    int n = nt * 8 + g;
    float w0 = __ldg(Wg + (size_t)l * HDIM * HDIM + k0 * HDIM + n);
    float w1 = __ldg(Wg + (size_t)l * HDIM * HDIM + (k0 + 1) * HDIM + n);
    __nv_bfloat16 v0, v1;
    if (s == 0) {
        v0 = __float2bfloat16(w0);
        v1 = __float2bfloat16(w1);
    } else {
        v0 = __float2bfloat16(w0 - __bfloat162float(__float2bfloat16(w0)));
        v1 = __float2bfloat16(w1 - __bfloat162float(__float2bfloat16(w1)));
    }
    uint32_t u = (uint32_t)*(uint16_t*)&v0 | ((uint32_t)*(uint16_t*)&v1 << 16);
    d_wfrag[i] = u;
}

// ---------------- K5: CSR gather: t16[n] = bf16(h16[n] + (sum_e h16[col]*ew) * inv) ----------------
// warp per node; lane = 4 channels; 8 edges per group (padded, branch-free).
__global__ __launch_bounds__(256) void gather_kernel(const float* __restrict__ We,
                                                     const float* __restrict__ be) {
    int lane = threadIdx.x & 31;
    int n = blockIdx.x * 8 + (threadIdx.x >> 5);

    float4 w0 = __ldg((const float4*)We + lane);
    float4 w1 = __ldg((const float4*)(We + HDIM) + lane);
    float4 bb = __ldg((const float4*)be + lane);

    int js = __ldg(d_start + n);
    int je = __ldg(d_start + n + 1);

    float4 acc = make_float4(0.f, 0.f, 0.f, 0.f);

    for (int j = js; j < je; j += 8) {
        uint2 er[8];
#pragma unroll
        for (int i = 0; i < 8; i++) er[i] = __ldg(d_edge + j + i);
        uint2 hv[8];
#pragma unroll
        for (int i = 0; i < 8; i++)
            hv[i] = __ldg((const uint2*)(d_h16 + (size_t)er[i].x * HDIM) + lane);
#pragma unroll
        for (int i = 0; i < 8; i++) {
            __half2 ah = *(__half2*)&er[i].y;
            float2 af = __half22float2(ah);
            float4 v = h16_to_f4(hv[i]);
            float4 e;
            e.x = fmaf(af.x, w0.x, fmaf(af.y, w1.x, bb.x));
            e.y = fmaf(af.x, w0.y, fmaf(af.y, w1.y, bb.y));
            e.z = fmaf(af.x, w0.z, fmaf(af.y, w1.z, bb.z));
            e.w = fmaf(af.x, w0.w, fmaf(af.y, w1.w, bb.w));
            acc.x = fmaf(v.x, e.x, acc.x);
            acc.y = fmaf(v.y, e.y, acc.y);
            acc.z = fmaf(v.z, e.z, acc.z);
            acc.w = fmaf(v.w, e.w, acc.w);
        }
    }

    float inv = __ldg(d_inv + n);
    float4 hv = h16_to_f4(__ldg((const uint2*)(d_h16 + (size_t)n * HDIM) + lane));
    float tx = fmaf(acc.x, inv, hv.x);
    float ty = fmaf(acc.y, inv, hv.y);
    float tz = fmaf(acc.z, inv, hv.z);
    float tw = fmaf(acc.w, inv, hv.w);
    __nv_bfloat162 p0 = __floats2bfloat162_rn(tx, ty);
    __nv_bfloat162 p1 = __floats2bfloat162_rn(tz, tw);
    ((uint2*)(d_t16 + (size_t)n * HDIM))[lane] = make_uint2(*(uint32_t*)&p0, *(uint32_t*)&p1);
}

// ---------------- K6: input GEMM (fma2, fp32): h16 = fp16(x @ W_in + b) ----------------
__global__ __launch_bounds__(256) void ingemm_kernel(const float* __restrict__ Ax,
                                                     const float* __restrict__ bias) {
    extern __shared__ float sAT[];  // [64][128] swizzled
    const int tid = threadIdx.x;
    const int tx = tid & 15;
    const int ty = tid >> 4;
    const int nb = blockIdx.x * 128;
    constexpr int K = DIN;
    constexpr int KQ = K / 4;

#pragma unroll
    for (int j = 0; j < K / 8; j++) {
        int q = tid + 256 * j;
        int n = q / KQ;
        int kq = q % KQ;
        float4 v = __ldcs((const float4*)&Ax[(size_t)(nb + n) * K + 4 * kq]);
        int pn = n ^ (2 * (kq & 15));
        sAT[(4 * kq + 0) * 128 + pn] = v.x;
        sAT[(4 * kq + 1) * 128 + pn] = v.y;
        sAT[(4 * kq + 2) * 128 + pn] = v.z;
        sAT[(4 * kq + 3) * 128 + pn] = v.w;
    }
    __syncthreads();

    unsigned long long acc[4][8];
#pragma unroll
    for (int p = 0; p < 4; p++)
#pragma unroll
        for (int c = 0; c < 8; c++) acc[p][c] = 0ull;

    const unsigned long long* Wp = d_wdup + tx * 8;

#pragma unroll 2
    for (int k = 0; k < K; k++) {
        const float* ar = sAT + k * 128;
        int sw = 2 * ((k >> 2) & 15);
        unsigned long long a[4];
#pragma unroll
        for (int p = 0; p < 4; p++)
            a[p] = *(const unsigned long long*)(ar + ((ty * 8 + 2 * p) ^ sw));
        ulonglong2 w01 = __ldg((const ulonglong2*)(Wp + (size_t)k * 128));
        ulonglong2 w23 = __ldg((const ulonglong2*)(Wp + (size_t)k * 128 + 2));
        ulonglong2 w45 = __ldg((const ulonglong2*)(Wp + (size_t)k * 128 + 4));
        ulonglong2 w67 = __ldg((const ulonglong2*)(Wp + (size_t)k * 128 + 6));
        unsigned long long w[8] = {w01.x, w01.y, w23.x, w23.y, w45.x, w45.y, w67.x, w67.y};
#pragma unroll
        for (int p = 0; p < 4; p++)
#pragma unroll
            for (int c = 0; c < 8; c++) fma2(acc[p][c], a[p], w[c]);
    }

    int c0 = tx * 8;
#pragma unroll
    for (int p = 0; p < 4; p++) {
        float lo[8], hi[8];
#pragma unroll
        for (int c = 0; c < 8; c++) {
            unpack2(acc[p][c], lo[c], hi[c]);
            lo[c] += __ldg(bias + c0 + c);
            hi[c] += __ldg(bias + c0 + c);
        }
        int r0 = nb + ty * 8 + 2 * p;
        __half2 hl[4], hh[4];
#pragma unroll
        for (int q = 0; q < 4; q++) {
            hl[q] = __floats2half2_rn(lo[2 * q], lo[2 * q + 1]);
            hh[q] = __floats2half2_rn(hi[2 * q], hi[2 * q + 1]);
        }
        *(uint4*)&d_h16[(size_t)r0 * HDIM + c0] = *(uint4*)hl;
        *(uint4*)&d_h16[(size_t)(r0 + 1) * HDIM + c0] = *(uint4*)hh;
    }
}

// ---------------- K7: mma.sync layer GEMM: h16 = fp16(relu(BN(t16 @ (Whi+Wlo) + b))) ----------------
#define SM_A_BYTES 34816                      // [128][136] bf16
#define SM_B_BYTES 65536                      // [2][8][16][32][2] u32
#define SM_TOT (SM_A_BYTES + SM_B_BYTES + 1024)
__global__ __launch_bounds__(256) void mmagemm_kernel(int layer,
                                                      const float* __restrict__ bias,
                                                      const float* __restrict__ gamma,
                                                      const float* __restrict__ beta,
                                                      const float* __restrict__ mean,
                                                      const float* __restrict__ var) {
    extern __shared__ char smem[];
    __nv_bfloat16* sA = (__nv_bfloat16*)smem;                 // stride 136
    uint32_t* sB = (uint32_t*)(smem + SM_A_BYTES);
    float* sBN = (float*)(smem + SM_A_BYTES + SM_B_BYTES);

    const int tid = threadIdx.x;
    const int lane = tid & 31;
    const int wid = tid >> 5;
    const int nb = blockIdx.x * 128;

    if (tid < 128) {
        float g = __ldg(gamma + tid);
        float v = __ldg(var + tid);
        float m = __ldg(mean + tid);
        float bt = __ldg(beta + tid);
        float b = __ldg(bias + tid);
        float sc = g * rsqrtf(v + EPSV);
        sBN[tid] = sc;
        sBN[128 + tid] = fmaf(b - m, sc, bt);
    }

    // stage A: raw bf16 copy [128][128] -> [128][136]
    const uint4* T = (const uint4*)(d_t16 + (size_t)nb * HDIM);
#pragma unroll
    for (int i = 0; i < 8; i++) {
        int q = tid + 256 * i;          // 0..2047 (uint4 = 8 bf16)
        int m = q >> 4, c0 = (q & 15) * 8;
        *(uint4*)(sA + m * 136 + c0) = __ldg(T + q);
    }
    // stage B frags (hi+lo, 64 KB)
    const uint4* BF = (const uint4*)(d_wfrag + layer * 16384);
#pragma unroll
    for (int i = 0; i < 16; i++) {
        int q = tid + 256 * i;
        ((uint4*)sB)[q] = __ldg(BF + q);
    }
    __syncthreads();

    const int g = lane >> 2, tg = lane & 3;
    float acc[16][4];
#pragma unroll
    for (int nt = 0; nt < 16; nt++)
#pragma unroll
        for (int c = 0; c < 4; c++) acc[nt][c] = 0.f;

    const __nv_bfloat16* ar0 = sA + (wid * 16 + g) * 136;
    const __nv_bfloat16* ar1 = ar0 + 8 * 136;

#pragma unroll
    for (int ks = 0; ks < 8; ks++) {
        int k0 = ks * 16 + tg * 2;
        uint32_t a0 = *(const uint32_t*)(ar0 + k0);
        uint32_t a1 = *(const uint32_t*)(ar1 + k0);
        uint32_t a2 = *(const uint32_t*)(ar0 + k0 + 8);
        uint32_t a3 = *(const uint32_t*)(ar1 + k0 + 8);
        const uint32_t* bh = sB + (ks * 16) * 64 + lane * 2;
        const uint32_t* bl = bh + 8 * 16 * 64;
#pragma unroll
        for (int nt = 0; nt < 16; nt++) {
            uint2 bhv = *(const uint2*)(bh + nt * 64);
            uint2 blv = *(const uint2*)(bl + nt * 64);
            mma_bf16(acc[nt], a0, a1, a2, a3, bhv.x, bhv.y);
            mma_bf16(acc[nt], a0, a1, a2, a3, blv.x, blv.y);
        }
    }

    int r0 = nb + wid * 16 + g;
    __half* om0 = d_h16 + (size_t)r0 * HDIM;
    __half* om1 = om0 + 8 * HDIM;
#pragma unroll
    for (int nt = 0; nt < 16; nt++) {
        int c = nt * 8 + tg * 2;
        float sc0 = sBN[c], sc1 = sBN[c + 1];
        float sh0 = sBN[128 + c], sh1 = sBN[128 + c + 1];
        float o00 = fmaxf(fmaf(acc[nt][0], sc0, sh0), 0.f);
        float o01 = fmaxf(fmaf(acc[nt][1], sc1, sh1), 0.f);
        float o10 = fmaxf(fmaf(acc[nt][2], sc0, sh0), 0.f);
        float o11 = fmaxf(fmaf(acc[nt][3], sc1, sh1), 0.f);
        *(__half2*)(om0 + c) = __floats2half2_rn(o00, o01);
        *(__half2*)(om1 + c) = __floats2half2_rn(o10, o11);
    }
}

// ---------------- K8: global mean-pool (batch sorted, reads h16) ----------------
__global__ __launch_bounds__(256) void pool_kernel(const int* __restrict__ batch) {
    int tx = threadIdx.x & 31;
    int ty = threadIdx.x >> 5;
    int base = blockIdx.x * 512;

    float4 acc = make_float4(0.f, 0.f, 0.f, 0.f);
    float cnt = 0.f;
    int curg = -1;

    for (int j = 0; j < 64; j++) {
        int n = base + ty + j * 8;
        int g = __ldg(batch + n);
        if (g != curg) {
            if (curg >= 0) {
                red4(d_gsum + curg * HDIM + 4 * tx, acc);
                if (tx == 0) atomicAdd(&d_gcnt[curg], cnt);
            }
            curg = g;
            acc = make_float4(0.f, 0.f, 0.f, 0.f);
            cnt = 0.f;
        }
        float4 h4 = h16_to_f4(((const uint2*)(d_h16 + (size_t)n * HDIM))[tx]);
        acc.x += h4.x; acc.y += h4.y; acc.z += h4.z; acc.w += h4.w;
        cnt += 1.f;
    }
    if (curg >= 0) {
        red4(d_gsum + curg * HDIM + 4 * tx, acc);
        if (tx == 0) atomicAdd(&d_gcnt[curg], cnt);
    }
}

// ---------------- K9: head ----------------
__global__ __launch_bounds__(128) void final_kernel(const float* __restrict__ gx,
                                                    const float* __restrict__ Wgp,
                                                    const float* __restrict__ bgp,
                                                    const float* __restrict__ Wgc,
                                                    const float* __restrict__ bgc,
                                                    float* __restrict__ out) {
    int g = blockIdx.x;
    int t = threadIdx.x;
    __shared__ float sg[HDIM];
    __shared__ float sgp[32];

    float c = fmaxf(__ldg(&d_gcnt[g]), 1.0f);
    sg[t] = d_gsum[g * HDIM + t] / c;
    if (t < 32) {
        float acc = __ldg(bgp + t);
        for (int d = 0; d < 6; d++)
            acc = fmaf(__ldg(gx + g * 6 + d), __ldg(Wgp + d * 32 + t), acc);
        sgp[t] = fmaxf(acc, 0.f);
    }
    __syncthreads();

    float acc = __ldg(bgc + t);
#pragma unroll 4
    for (int k = 0; k < HDIM; k++)
        acc = fmaf(sg[k], __ldg(Wgc + (size_t)k * HDIM + t), acc);
#pragma unroll 4
    for (int k = 0; k < 32; k++)
        acc = fmaf(sgp[k], __ldg(Wgc + (size_t)(HDIM + k) * HDIM + t), acc);
    out[g * HDIM + t] = acc;
}

// ---------------- launch ----------------
extern "C" void kernel_launch(void* const* d_in, const int* in_sizes, int n_in,
                              void* d_out, int out_size) {
    const float* x       = (const float*)d_in[0];
    const float* eattr   = (const float*)d_in[1];
    const float* gx      = (const float*)d_in[2];
    const float* W_in    = (const float*)d_in[3];
    const float* b_in    = (const float*)d_in[4];
    const float* W_edge  = (const float*)d_in[5];
    const float* b_edge  = (const float*)d_in[6];
    const float* W_gcn   = (const float*)d_in[7];
    const float* b_gcn   = (const float*)d_in[8];
    const float* bn_g    = (const float*)d_in[9];
    const float* bn_b    = (const float*)d_in[10];
    const float* bn_m    = (const float*)d_in[11];
    const float* bn_v    = (const float*)d_in[12];
    const float* W_gproj = (const float*)d_in[13];
    const float* b_gproj = (const float*)d_in[14];
    const float* W_gcomb = (const float*)d_in[15];
    const float* b_gcomb = (const float*)d_in[16];
    const int*   row     = (const int*)d_in[17];
    const int*   col     = (const int*)d_in[18];
    const int*   batch   = (const int*)d_in[19];
    float* out = (float*)d_out;

    cudaFuncSetAttribute(ingemm_kernel, cudaFuncAttributeMaxDynamicSharedMemorySize,
                         DIN * 128 * 4);
    cudaFuncSetAttribute(mmagemm_kernel, cudaFuncAttributeMaxDynamicSharedMemorySize,
                         SM_TOT);

    zero_kernel<<<512, 256>>>();
    fill_kernel<<<E_PAD / 256, 256>>>();
    deg_kernel<<<N_EDGES / 256, 256>>>(row);
    scanA_kernel<<<128, 256>>>();
    scanB_kernel<<<1, 128>>>();
    scanC_kernel<<<128, 256>>>();
    build_kernel<<<N_EDGES / 256, 256>>>(row, col, eattr);
    wdup_kernel<<<DIN * HDIM / 256, 256>>>(W_in);
    wfrag_kernel<<<192, 256>>>(W_gcn);

    ingemm_kernel<<<N_NODES / 128, 256, DIN * 128 * 4>>>(x, b_in);

    for (int l = 0; l < 3; l++) {
        gather_kernel<<<N_NODES / 8, 256>>>(W_edge, b_edge);
        mmagemm_kernel<<<N_NODES / 128, 256, SM_TOT>>>(
            l, b_gcn + l * HDIM,
            bn_g + l * HDIM, bn_b + l * HDIM, bn_m + l * HDIM, bn_v + l * HDIM);
    }

    pool_kernel<<<N_NODES / 512, 256>>>(batch);
    final_kernel<<<N_GRAPHS, HDIM>>>(gx, W_gproj, b_gproj, W_gcomb, b_gcomb, out);
}

// round 7
// speedup vs baseline: 3.2854x; 1.1518x over previous
#include <cuda_runtime.h>
#include <cuda_fp16.h>
#include <cuda_bf16.h>
#include <cstdint>

#define N_NODES 131072
#define N_EDGES 2097152
#define E_PAD   (N_EDGES + 16 * N_NODES)   // padded CSR slots (pad-to-16)
#define N_GRAPHS 64
#define DIN 64
#define HDIM 128
#define EPSV 1e-5f

// ---------------- scratch (device globals: allocation-free) ----------------
__device__ __align__(128) __half d_h16[((size_t)N_NODES + 1) * HDIM];  // 32 MB + sentinel row
__device__ __align__(128) __nv_bfloat16 d_t16[(size_t)N_NODES * HDIM]; // 32 MB
__device__ __align__(128) uint2  d_edge[E_PAD];                        // {col, half2 attr} 32 MB
__device__ __align__(128) int    d_degi[N_NODES];
__device__ __align__(128) int    d_cnt[N_NODES];
__device__ __align__(128) int    d_start[N_NODES + 1];
__device__ __align__(128) float  d_inv[N_NODES];
__device__ __align__(128) int    d_bsum[128];
__device__ __align__(128) int    d_bbase[128];
// layer GEMM B-fragments: [layer][hi/lo][kstep 8][ntile 16][lane 32][reg 2]
__device__ __align__(128) uint32_t d_wfrag[3 * 2 * 8 * 16 * 32 * 2];
// input GEMM B-fragments: [hi/lo][kstep 4][ntile 16][lane 32][reg 2]
__device__ __align__(128) uint32_t d_wfragin[2 * 4 * 16 * 32 * 2];
__device__ __align__(128) float  d_gsum[N_GRAPHS * HDIM];
__device__ __align__(128) float  d_gcnt[N_GRAPHS];

// ---------------- helpers ----------------
__device__ __forceinline__ void red4(float* p, float4 v) {
    asm volatile("red.global.add.v4.f32 [%0], {%1,%2,%3,%4};"
                 :: "l"(p), "f"(v.x), "f"(v.y), "f"(v.z), "f"(v.w) : "memory");
}
__device__ __forceinline__ float4 h16_to_f4(uint2 u) {
    __half2* p = (__half2*)&u;
    float2 f0 = __half22float2(p[0]);
    float2 f1 = __half22float2(p[1]);
    return make_float4(f0.x, f0.y, f1.x, f1.y);
}
__device__ __forceinline__ void mma_bf16(float* d, uint32_t a0, uint32_t a1, uint32_t a2,
                                         uint32_t a3, uint32_t b0, uint32_t b1) {
    asm volatile(
        "mma.sync.aligned.m16n8k16.row.col.f32.bf16.bf16.f32 "
        "{%0,%1,%2,%3}, {%4,%5,%6,%7}, {%8,%9}, {%0,%1,%2,%3};"
        : "+f"(d[0]), "+f"(d[1]), "+f"(d[2]), "+f"(d[3])
        : "r"(a0), "r"(a1), "r"(a2), "r"(a3), "r"(b0), "r"(b1));
}

// ---------------- K0: zero counters + sentinel h16 row ----------------
__global__ void zero_kernel() {
    int i = blockIdx.x * blockDim.x + threadIdx.x;
    if (i < N_NODES) { d_degi[i] = 0; d_cnt[i] = 0; }
    if (i < N_GRAPHS * HDIM) d_gsum[i] = 0.0f;
    if (i < N_GRAPHS) d_gcnt[i] = 0.0f;
    if (i < 16) ((uint4*)(d_h16 + (size_t)N_NODES * HDIM))[i] = make_uint4(0, 0, 0, 0);
}

// ---------------- K0b: fill edge table with sentinel records ----------------
__global__ void fill_kernel() {
    int i = blockIdx.x * blockDim.x + threadIdx.x;
    d_edge[i] = make_uint2((uint32_t)N_NODES, 0u);
}

// ---------------- K1: degree count ----------------
__global__ void deg_kernel(const int* __restrict__ row) {
    int e = blockIdx.x * blockDim.x + threadIdx.x;
    atomicAdd(&d_degi[row[e]], 1);
}

// ---------------- K2a/b/c: exclusive scan of PADDED deg (pad 16) ----------------
__global__ __launch_bounds__(256) void scanA_kernel() {
    __shared__ int sp[256];
    int tid = threadIdx.x;
    int4 dv = ((const int4*)d_degi)[blockIdx.x * 256 + tid];
    int s = ((dv.x + 15) & ~15) + ((dv.y + 15) & ~15) + ((dv.z + 15) & ~15) + ((dv.w + 15) & ~15);
    sp[tid] = s;
    __syncthreads();
    for (int off = 128; off > 0; off >>= 1) {
        if (tid < off) sp[tid] += sp[tid + off];
        __syncthreads();
    }
    if (tid == 0) d_bsum[blockIdx.x] = sp[0];
}

__global__ __launch_bounds__(128) void scanB_kernel() {
    __shared__ int sp[128];
    int tid = threadIdx.x;
    int s = d_bsum[tid];
    sp[tid] = s;
    __syncthreads();
    for (int off = 1; off < 128; off <<= 1) {
        int v = (tid >= off) ? sp[tid - off] : 0;
        __syncthreads();
        sp[tid] += v;
        __syncthreads();
    }
    d_bbase[tid] = sp[tid] - s;
    if (tid == 127) d_start[N_NODES] = sp[127];
}

__global__ __launch_bounds__(256) void scanC_kernel() {
    __shared__ int sp[256];
    int tid = threadIdx.x;
    int idx = blockIdx.x * 256 + tid;
    int4 dv = ((const int4*)d_degi)[idx];
    int p0 = (dv.x + 15) & ~15, p1 = (dv.y + 15) & ~15;
    int p2 = (dv.z + 15) & ~15, p3 = (dv.w + 15) & ~15;
    int s = p0 + p1 + p2 + p3;
    sp[tid] = s;
    __syncthreads();
    for (int off = 1; off < 256; off <<= 1) {
        int v = (tid >= off) ? sp[tid - off] : 0;
        __syncthreads();
        sp[tid] += v;
        __syncthreads();
    }
    int base = d_bbase[blockIdx.x] + sp[tid] - s;
    int4 st;
    st.x = base;
    st.y = base + p0;
    st.z = st.y + p1;
    st.w = st.z + p2;
    ((int4*)d_start)[idx] = st;
    float4 iv;
    iv.x = 1.0f / (float)max(dv.x, 1);
    iv.y = 1.0f / (float)max(dv.y, 1);
    iv.z = 1.0f / (float)max(dv.z, 1);
    iv.w = 1.0f / (float)max(dv.w, 1);
    ((float4*)d_inv)[idx] = iv;
}

// ---------------- K3: counting-sort edges into padded CSR ----------------
__global__ __launch_bounds__(256) void build_kernel(const int* __restrict__ row,
                                                    const int* __restrict__ col,
                                                    const float* __restrict__ eattr) {
    int e = blockIdx.x * blockDim.x + threadIdx.x;
    int r = __ldg(row + e);
    int pos = __ldg(d_start + r) + atomicAdd(&d_cnt[r], 1);
    float2 a = __ldg((const float2*)eattr + e);
    __half2 ah = __floats2half2_rn(a.x, a.y);
    d_edge[pos] = make_uint2((uint32_t)__ldg(col + e), *(uint32_t*)&ah);
}

// ---------------- K4a: layer GEMM B-fragments (W hi/lo bf16) ----------------
__global__ __launch_bounds__(256) void wfrag_kernel(const float* __restrict__ Wg) {
    int i = blockIdx.x * blockDim.x + threadIdx.x;  // < 49152
    int r = i & 1;
    int lane = (i >> 1) & 31;
    int nt = (i >> 6) & 15;
    int ks = (i >> 10) & 7;
    int s = (i >> 13) & 1;
    int l = i >> 14;
    int tg = lane & 3;
    int g = lane >> 2;
    int k0 = ks * 16 + tg * 2 + r * 8;
    int n = nt * 8 + g;
    float w0 = __ldg(Wg + (size_t)l * HDIM * HDIM + k0 * HDIM + n);
    float w1 = __ldg(Wg + (size_t)l * HDIM * HDIM + (k0 + 1) * HDIM + n);
    __nv_bfloat16 v0, v1;
    if (s == 0) {
        v0 = __float2bfloat16(w0);
        v1 = __float2bfloat16(w1);
    } else {
        v0 = __float2bfloat16(w0 - __bfloat162float(__float2bfloat16(w0)));
        v1 = __float2bfloat16(w1 - __bfloat162float(__float2bfloat16(w1)));
    }
    d_wfrag[i] = (uint32_t)*(uint16_t*)&v0 | ((uint32_t)*(uint16_t*)&v1 << 16);
}

// ---------------- K4b: input GEMM B-fragments (W_in hi/lo bf16, K=64) ----------------
__global__ __launch_bounds__(256) void wfragin_kernel(const float* __restrict__ Win) {
    int i = blockIdx.x * blockDim.x + threadIdx.x;  // < 8192
    int r = i & 1;
    int lane = (i >> 1) & 31;
    int nt = (i >> 6) & 15;
    int ks = (i >> 10) & 3;
    int s = (i >> 12) & 1;
    int tg = lane & 3;
    int g = lane >> 2;
    int k0 = ks * 16 + tg * 2 + r * 8;
    int n = nt * 8 + g;
    float w0 = __ldg(Win + k0 * HDIM + n);
    float w1 = __ldg(Win + (k0 + 1) * HDIM + n);
    __nv_bfloat16 v0, v1;
    if (s == 0) {
        v0 = __float2bfloat16(w0);
        v1 = __float2bfloat16(w1);
    } else {
        v0 = __float2bfloat16(w0 - __bfloat162float(__float2bfloat16(w0)));
        v1 = __float2bfloat16(w1 - __bfloat162float(__float2bfloat16(w1)));
    }
    d_wfragin[i] = (uint32_t)*(uint16_t*)&v0 | ((uint32_t)*(uint16_t*)&v1 << 16);
}

// ---------------- K5: CSR gather, 16 edges in flight (padded, branch-free) ----------------
__global__ __launch_bounds__(256) void gather_kernel(const float* __restrict__ We,
                                                     const float* __restrict__ be) {
    int lane = threadIdx.x & 31;
    int n = blockIdx.x * 8 + (threadIdx.x >> 5);

    float4 w0 = __ldg((const float4*)We + lane);
    float4 w1 = __ldg((const float4*)(We + HDIM) + lane);
    float4 bb = __ldg((const float4*)be + lane);

    int js = __ldg(d_start + n);
    int je = __ldg(d_start + n + 1);

    float4 acc = make_float4(0.f, 0.f, 0.f, 0.f);

    for (int j = js; j < je; j += 16) {
        uint2 er[16];
#pragma unroll
        for (int i = 0; i < 16; i++) er[i] = __ldg(d_edge + j + i);
        uint2 hv[16];
#pragma unroll
        for (int i = 0; i < 16; i++)
            hv[i] = __ldg((const uint2*)(d_h16 + (size_t)er[i].x * HDIM) + lane);
#pragma unroll
        for (int i = 0; i < 16; i++) {
            __half2 ah = *(__half2*)&er[i].y;
            float2 af = __half22float2(ah);
            float4 v = h16_to_f4(hv[i]);
            float4 e;
            e.x = fmaf(af.x, w0.x, fmaf(af.y, w1.x, bb.x));
            e.y = fmaf(af.x, w0.y, fmaf(af.y, w1.y, bb.y));
            e.z = fmaf(af.x, w0.z, fmaf(af.y, w1.z, bb.z));
            e.w = fmaf(af.x, w0.w, fmaf(af.y, w1.w, bb.w));
            acc.x = fmaf(v.x, e.x, acc.x);
            acc.y = fmaf(v.y, e.y, acc.y);
            acc.z = fmaf(v.z, e.z, acc.z);
            acc.w = fmaf(v.w, e.w, acc.w);
        }
    }

    float inv = __ldg(d_inv + n);
    float4 hv = h16_to_f4(__ldg((const uint2*)(d_h16 + (size_t)n * HDIM) + lane));
    float tx = fmaf(acc.x, inv, hv.x);
    float ty = fmaf(acc.y, inv, hv.y);
    float tz = fmaf(acc.z, inv, hv.z);
    float tw = fmaf(acc.w, inv, hv.w);
    __nv_bfloat162 p0 = __floats2bfloat162_rn(tx, ty);
    __nv_bfloat162 p1 = __floats2bfloat162_rn(tz, tw);
    ((uint2*)(d_t16 + (size_t)n * HDIM))[lane] = make_uint2(*(uint32_t*)&p0, *(uint32_t*)&p1);
}

// ---------------- K6: input GEMM via mma: h16 = fp16(bf16(x) @ (Whi+Wlo) + b) ----------------
#define SMI_A_BYTES (128 * 72 * 2)            // [128][72] bf16 = 18432
#define SMI_B_BYTES 32768                     // [2][4][16][32][2] u32
#define SMI_TOT (SMI_A_BYTES + SMI_B_BYTES)
__global__ __launch_bounds__(256) void ingemm_kernel(const float* __restrict__ Ax,
                                                     const float* __restrict__ bias) {
    extern __shared__ char smem[];
    __nv_bfloat16* sA = (__nv_bfloat16*)smem;        // stride 72
    uint32_t* sB = (uint32_t*)(smem + SMI_A_BYTES);

    const int tid = threadIdx.x;
    const int lane = tid & 31;
    const int wid = tid >> 5;
    const int nb = blockIdx.x * 128;

    // stage A: x fp32 [128][64] -> bf16 [128][72]
    const float4* X = (const float4*)(Ax + (size_t)nb * DIN);
#pragma unroll
    for (int i = 0; i < 8; i++) {
        int q = tid + 256 * i;          // 0..2047
        int m = q >> 4, c0 = (q & 15) * 4;
        float4 v = __ldcs(X + q);
        __nv_bfloat162 p0 = __floats2bfloat162_rn(v.x, v.y);
        __nv_bfloat162 p1 = __floats2bfloat162_rn(v.z, v.w);
        *(uint2*)(sA + m * 72 + c0) = make_uint2(*(uint32_t*)&p0, *(uint32_t*)&p1);
    }
    // stage B frags (hi+lo, 32 KB)
    const uint4* BF = (const uint4*)d_wfragin;
#pragma unroll
    for (int i = 0; i < 8; i++) {
        int q = tid + 256 * i;          // 0..2047
        ((uint4*)sB)[q] = __ldg(BF + q);
    }
    __syncthreads();

    const int g = lane >> 2, tg = lane & 3;
    float acc[16][4];
#pragma unroll
    for (int nt = 0; nt < 16; nt++)
#pragma unroll
        for (int c = 0; c < 4; c++) acc[nt][c] = 0.f;

    const __nv_bfloat16* ar0 = sA + (wid * 16 + g) * 72;
    const __nv_bfloat16* ar1 = ar0 + 8 * 72;

#pragma unroll
    for (int ks = 0; ks < 4; ks++) {
        int k0 = ks * 16 + tg * 2;
        uint32_t a0 = *(const uint32_t*)(ar0 + k0);
        uint32_t a1 = *(const uint32_t*)(ar1 + k0);
        uint32_t a2 = *(const uint32_t*)(ar0 + k0 + 8);
        uint32_t a3 = *(const uint32_t*)(ar1 + k0 + 8);
        const uint32_t* bh = sB + (ks * 16) * 64 + lane * 2;
        const uint32_t* bl = bh + 4 * 16 * 64;
#pragma unroll
        for (int nt = 0; nt < 16; nt++) {
            uint2 bhv = *(const uint2*)(bh + nt * 64);
            uint2 blv = *(const uint2*)(bl + nt * 64);
            mma_bf16(acc[nt], a0, a1, a2, a3, bhv.x, bhv.y);
            mma_bf16(acc[nt], a0, a1, a2, a3, blv.x, blv.y);
        }
    }

    int r0 = nb + wid * 16 + g;
    __half* om0 = d_h16 + (size_t)r0 * HDIM;
    __half* om1 = om0 + 8 * HDIM;
#pragma unroll
    for (int nt = 0; nt < 16; nt++) {
        int c = nt * 8 + tg * 2;
        float b0 = __ldg(bias + c), b1 = __ldg(bias + c + 1);
        *(__half2*)(om0 + c) = __floats2half2_rn(acc[nt][0] + b0, acc[nt][1] + b1);
        *(__half2*)(om1 + c) = __floats2half2_rn(acc[nt][2] + b0, acc[nt][3] + b1);
    }
}

// ---------------- K7: mma.sync layer GEMM: h16 = fp16(relu(BN(t16 @ (Whi+Wlo) + b))) ----------------
#define SM_A_BYTES 34816                      // [128][136] bf16
#define SM_B_BYTES 65536                      // [2][8][16][32][2] u32
#define SM_TOT (SM_A_BYTES + SM_B_BYTES + 1024)
__global__ __launch_bounds__(256) void mmagemm_kernel(int layer,
                                                      const float* __restrict__ bias,
                                                      const float* __restrict__ gamma,
                                                      const float* __restrict__ beta,
                                                      const float* __restrict__ mean,
                                                      const float* __restrict__ var) {
    extern __shared__ char smem[];
    __nv_bfloat16* sA = (__nv_bfloat16*)smem;                 // stride 136
    uint32_t* sB = (uint32_t*)(smem + SM_A_BYTES);
    float* sBN = (float*)(smem + SM_A_BYTES + SM_B_BYTES);

    const int tid = threadIdx.x;
    const int lane = tid & 31;
    const int wid = tid >> 5;
    const int nb = blockIdx.x * 128;

    if (tid < 128) {
        float g = __ldg(gamma + tid);
        float v = __ldg(var + tid);
        float m = __ldg(mean + tid);
        float bt = __ldg(beta + tid);
        float b = __ldg(bias + tid);
        float sc = g * rsqrtf(v + EPSV);
        sBN[tid] = sc;
        sBN[128 + tid] = fmaf(b - m, sc, bt);
    }

    // stage A: raw bf16 copy [128][128] -> [128][136]
    const uint4* T = (const uint4*)(d_t16 + (size_t)nb * HDIM);
#pragma unroll
    for (int i = 0; i < 8; i++) {
        int q = tid + 256 * i;          // 0..2047 (uint4 = 8 bf16)
        int m = q >> 4, c0 = (q & 15) * 8;
        *(uint4*)(sA + m * 136 + c0) = __ldg(T + q);
    }
    // stage B frags (hi+lo, 64 KB)
    const uint4* BF = (const uint4*)(d_wfrag + layer * 16384);
#pragma unroll
    for (int i = 0; i < 16; i++) {
        int q = tid + 256 * i;
        ((uint4*)sB)[q] = __ldg(BF + q);
    }
    __syncthreads();

    const int g = lane >> 2, tg = lane & 3;
    float acc[16][4];
#pragma unroll
    for (int nt = 0; nt < 16; nt++)
#pragma unroll
        for (int c = 0; c < 4; c++) acc[nt][c] = 0.f;

    const __nv_bfloat16* ar0 = sA + (wid * 16 + g) * 136;
    const __nv_bfloat16* ar1 = ar0 + 8 * 136;

#pragma unroll
    for (int ks = 0; ks < 8; ks++) {
        int k0 = ks * 16 + tg * 2;
        uint32_t a0 = *(const uint32_t*)(ar0 + k0);
        uint32_t a1 = *(const uint32_t*)(ar1 + k0);
        uint32_t a2 = *(const uint32_t*)(ar0 + k0 + 8);
        uint32_t a3 = *(const uint32_t*)(ar1 + k0 + 8);
        const uint32_t* bh = sB + (ks * 16) * 64 + lane * 2;
        const uint32_t* bl = bh + 8 * 16 * 64;
#pragma unroll
        for (int nt = 0; nt < 16; nt++) {
            uint2 bhv = *(const uint2*)(bh + nt * 64);
            uint2 blv = *(const uint2*)(bl + nt * 64);
            mma_bf16(acc[nt], a0, a1, a2, a3, bhv.x, bhv.y);
            mma_bf16(acc[nt], a0, a1, a2, a3, blv.x, blv.y);
        }
    }

    int r0 = nb + wid * 16 + g;
    __half* om0 = d_h16 + (size_t)r0 * HDIM;
    __half* om1 = om0 + 8 * HDIM;
#pragma unroll
    for (int nt = 0; nt < 16; nt++) {
        int c = nt * 8 + tg * 2;
        float sc0 = sBN[c], sc1 = sBN[c + 1];
        float sh0 = sBN[128 + c], sh1 = sBN[128 + c + 1];
        float o00 = fmaxf(fmaf(acc[nt][0], sc0, sh0), 0.f);
        float o01 = fmaxf(fmaf(acc[nt][1], sc1, sh1), 0.f);
        float o10 = fmaxf(fmaf(acc[nt][2], sc0, sh0), 0.f);
        float o11 = fmaxf(fmaf(acc[nt][3], sc1, sh1), 0.f);
        *(__half2*)(om0 + c) = __floats2half2_rn(o00, o01);
        *(__half2*)(om1 + c) = __floats2half2_rn(o10, o11);
    }
}

// ---------------- K8: global mean-pool (batch sorted, reads h16) ----------------
__global__ __launch_bounds__(256) void pool_kernel(const int* __restrict__ batch) {
    int tx = threadIdx.x & 31;
    int ty = threadIdx.x >> 5;
    int base = blockIdx.x * 512;

    float4 acc = make_float4(0.f, 0.f, 0.f, 0.f);
    float cnt = 0.f;
    int curg = -1;

    for (int j = 0; j < 64; j++) {
        int n = base + ty + j * 8;
        int g = __ldg(batch + n);
        if (g != curg) {
            if (curg >= 0) {
                red4(d_gsum + curg * HDIM + 4 * tx, acc);
                if (tx == 0) atomicAdd(&d_gcnt[curg], cnt);
            }
            curg = g;
            acc = make_float4(0.f, 0.f, 0.f, 0.f);
            cnt = 0.f;
        }
        float4 h4 = h16_to_f4(((const uint2*)(d_h16 + (size_t)n * HDIM))[tx]);
        acc.x += h4.x; acc.y += h4.y; acc.z += h4.z; acc.w += h4.w;
        cnt += 1.f;
    }
    if (curg >= 0) {
        red4(d_gsum + curg * HDIM + 4 * tx, acc);
        if (tx == 0) atomicAdd(&d_gcnt[curg], cnt);
    }
}

// ---------------- K9: head ----------------
__global__ __launch_bounds__(128) void final_kernel(const float* __restrict__ gx,
                                                    const float* __restrict__ Wgp,
                                                    const float* __restrict__ bgp,
                                                    const float* __restrict__ Wgc,
                                                    const float* __restrict__ bgc,
                                                    float* __restrict__ out) {
    int g = blockIdx.x;
    int t = threadIdx.x;
    __shared__ float sg[HDIM];
    __shared__ float sgp[32];

    float c = fmaxf(__ldg(&d_gcnt[g]), 1.0f);
    sg[t] = d_gsum[g * HDIM + t] / c;
    if (t < 32) {
        float acc = __ldg(bgp + t);
        for (int d = 0; d < 6; d++)
            acc = fmaf(__ldg(gx + g * 6 + d), __ldg(Wgp + d * 32 + t), acc);
        sgp[t] = fmaxf(acc, 0.f);
    }
    __syncthreads();

    float acc = __ldg(bgc + t);
#pragma unroll 4
    for (int k = 0; k < HDIM; k++)
        acc = fmaf(sg[k], __ldg(Wgc + (size_t)k * HDIM + t), acc);
#pragma unroll 4
    for (int k = 0; k < 32; k++)
        acc = fmaf(sgp[k], __ldg(Wgc + (size_t)(HDIM + k) * HDIM + t), acc);
    out[g * HDIM + t] = acc;
}

// ---------------- launch ----------------
extern "C" void kernel_launch(void* const* d_in, const int* in_sizes, int n_in,
                              void* d_out, int out_size) {
    const float* x       = (const float*)d_in[0];
    const float* eattr   = (const float*)d_in[1];
    const float* gx      = (const float*)d_in[2];
    const float* W_in    = (const float*)d_in[3];
    const float* b_in    = (const float*)d_in[4];
    const float* W_edge  = (const float*)d_in[5];
    const float* b_edge  = (const float*)d_in[6];
    const float* W_gcn   = (const float*)d_in[7];
    const float* b_gcn   = (const float*)d_in[8];
    const float* bn_g    = (const float*)d_in[9];
    const float* bn_b    = (const float*)d_in[10];
    const float* bn_m    = (const float*)d_in[11];
    const float* bn_v    = (const float*)d_in[12];
    const float* W_gproj = (const float*)d_in[13];
    const float* b_gproj = (const float*)d_in[14];
    const float* W_gcomb = (const float*)d_in[15];
    const float* b_gcomb = (const float*)d_in[16];
    const int*   row     = (const int*)d_in[17];
    const int*   col     = (const int*)d_in[18];
    const int*   batch   = (const int*)d_in[19];
    float* out = (float*)d_out;

    cudaFuncSetAttribute(ingemm_kernel, cudaFuncAttributeMaxDynamicSharedMemorySize,
                         SMI_TOT);
    cudaFuncSetAttribute(mmagemm_kernel, cudaFuncAttributeMaxDynamicSharedMemorySize,
                         SM_TOT);

    zero_kernel<<<512, 256>>>();
    fill_kernel<<<E_PAD / 256, 256>>>();
    deg_kernel<<<N_EDGES / 256, 256>>>(row);
    scanA_kernel<<<128, 256>>>();
    scanB_kernel<<<1, 128>>>();
    scanC_kernel<<<128, 256>>>();
    build_kernel<<<N_EDGES / 256, 256>>>(row, col, eattr);
    wfrag_kernel<<<192, 256>>>(W_gcn);
    wfragin_kernel<<<32, 256>>>(W_in);

    ingemm_kernel<<<N_NODES / 128, 256, SMI_TOT>>>(x, b_in);

    for (int l = 0; l < 3; l++) {
        gather_kernel<<<N_NODES / 8, 256>>>(W_edge, b_edge);
        mmagemm_kernel<<<N_NODES / 128, 256, SM_TOT>>>(
            l, b_gcn + l * HDIM,
            bn_g + l * HDIM, bn_b + l * HDIM, bn_m + l * HDIM, bn_v + l * HDIM);
    }

    pool_kernel<<<N_NODES / 512, 256>>>(batch);
    final_kernel<<<N_GRAPHS, HDIM>>>(gx, W_gproj, b_gproj, W_gcomb, b_gcomb, out);
}